// round 13
// baseline (speedup 1.0000x reference)
#include <cuda_runtime.h>
#include <math.h>
#include <stdint.h>

#define Bz   8
#define Nseq 4096
#define DIMC 768
#define Hh   12
#define Dh   64
#define BH   (Bz*Hh)        // 96
#define MR   (Bz*Nseq)      // 32768

// ---------------- scratch (device globals; no allocations allowed) ----------
__device__ float g_q[BH*Nseq*Dh];
__device__ float g_k[BH*Nseq*Dh];
__device__ float g_v[BH*Nseq*Dh];
__device__ float g_kcA[BH*2048*Dh];
__device__ float g_kcB[BH*1024*Dh];
__device__ float g_vc[BH*512*Dh];
__device__ float g_kv[BH*Dh*Dh];
__device__ float g_ksum[BH*Dh];
__device__ float g_attn[MR*DIMC];          // holds tf32 bit-patterns (as float)
__device__ uint32_t g_xt[MR*DIMC];         // X pre-converted to tf32 bits
__device__ uint32_t g_wqt[DIMC*DIMC];
__device__ uint32_t g_wkt[DIMC*DIMC];
__device__ uint32_t g_wvt[DIMC*DIMC];
__device__ uint32_t g_wot[DIMC*DIMC];

__device__ __forceinline__ float gelu_f(float t) {
    return 0.5f * t * (1.0f + erff(t * 0.70710678118654752f));
}
__device__ __forceinline__ float fmap_f(float t) {   // elu(t)+1
    return t > 0.0f ? t + 1.0f : expf(t);
}
__device__ __forceinline__ uint32_t f2tf32(float f) {
    uint32_t r;
    asm("cvt.rna.tf32.f32 %0, %1;" : "=r"(r) : "f"(f));
    return r;
}
__device__ __forceinline__ void mma_tf32(float c[4],
    uint32_t a0, uint32_t a1, uint32_t a2, uint32_t a3,
    uint32_t b0, uint32_t b1)
{
    asm volatile(
        "mma.sync.aligned.m16n8k8.row.col.f32.tf32.tf32.f32 "
        "{%0,%1,%2,%3}, {%4,%5,%6,%7}, {%8,%9}, {%0,%1,%2,%3};"
        : "+f"(c[0]), "+f"(c[1]), "+f"(c[2]), "+f"(c[3])
        : "r"(a0), "r"(a1), "r"(a2), "r"(a3), "r"(b0), "r"(b1));
}
__device__ __forceinline__ void cp_async16(uint32_t dst, const void* src) {
    asm volatile("cp.async.cg.shared.global [%0], [%1], 16;" :: "r"(dst), "l"(src));
}

// ---------------- prepass: fp32 -> tf32 bit patterns ------------------------
__global__ void prep_x(const float4* __restrict__ src)
{
    int i = blockIdx.x * 256 + threadIdx.x;
    if (i < MR * DIMC / 4) {
        float4 v = src[i];
        uint4 o;
        o.x = f2tf32(v.x); o.y = f2tf32(v.y);
        o.z = f2tf32(v.z); o.w = f2tf32(v.w);
        ((uint4*)g_xt)[i] = o;
    }
}
__global__ void prep_w(const float4* __restrict__ wq, const float4* __restrict__ wk,
                       const float4* __restrict__ wv, const float4* __restrict__ wo)
{
    const int n4 = DIMC * DIMC / 4;
    int i = blockIdx.x * 256 + threadIdx.x;
    if (i >= 4 * n4) return;
    int seg = i / n4, r = i - seg * n4;
    const float4* s = (seg == 0) ? wq : (seg == 1) ? wk : (seg == 2) ? wv : wo;
    uint4* d = (seg == 0) ? (uint4*)g_wqt : (seg == 1) ? (uint4*)g_wkt
             : (seg == 2) ? (uint4*)g_wvt : (uint4*)g_wot;
    float4 v = s[r];
    uint4 o;
    o.x = f2tf32(v.x); o.y = f2tf32(v.y);
    o.z = f2tf32(v.z); o.w = f2tf32(v.w);
    d[r] = o;
}

// =======================================================================
// Big GEMMs: tf32, cp.async double-buffered for BOTH A and B.
// =======================================================================
#define AS_STRIDE 36
#define BS_STRIDE 136
#define AS_TILE   (128 * AS_STRIDE)
#define BS_TILE   (32 * BS_STRIDE)
#define NT        (DIMC / 32)
#define GEMM_SMEM_BYTES ((2 * AS_TILE + 2 * BS_TILE) * 4)

#define GEMM_PROLOG \
    extern __shared__ uint32_t smemg[]; \
    uint32_t* Asf = smemg; \
    uint32_t* Bsf = smemg + 2 * AS_TILE; \
    uint32_t As_base = (uint32_t)__cvta_generic_to_shared(Asf); \
    uint32_t Bs_base = (uint32_t)__cvta_generic_to_shared(Bsf); \
    int tid = threadIdx.x; \
    int warp = tid >> 5, lane = tid & 31; \
    int g = lane >> 2, t = lane & 3; \
    int wm = warp >> 1, wn = warp & 1; \
    int a_row = tid >> 1, a_col = (tid & 1) << 4; \
    int b_row = tid >> 3, b_col = (tid & 7) << 4; \
    float acc[2][8][4]; \
    _Pragma("unroll") \
    for (int i = 0; i < 2; i++) \
        _Pragma("unroll") \
        for (int j = 0; j < 8; j++) \
            _Pragma("unroll") \
            for (int q = 0; q < 4; q++) acc[i][j][q] = 0.0f;

#define GEMM_CPLOAD(APTR_BASE, K0, BUF) { \
    const uint32_t* ap_ = (APTR_BASE) + (K0) + a_col; \
    const uint32_t* bp_ = W + (size_t)((K0) + b_row) * DIMC + n0 + b_col; \
    uint32_t asd = As_base + (uint32_t)(((BUF) * AS_TILE + a_row * AS_STRIDE + a_col) * 4); \
    uint32_t bsd = Bs_base + (uint32_t)(((BUF) * BS_TILE + b_row * BS_STRIDE + b_col) * 4); \
    _Pragma("unroll") \
    for (int u = 0; u < 4; u++) { \
        cp_async16(asd + u * 16, ap_ + u * 4); \
        cp_async16(bsd + u * 16, bp_ + u * 4); \
    } }

#define GEMM_COMPUTE(BUF) { \
    const uint32_t* Asc = Asf + (BUF) * AS_TILE; \
    const uint32_t* Bsc = Bsf + (BUF) * BS_TILE; \
    _Pragma("unroll") \
    for (int kk = 0; kk < 4; kk++) { \
        int ks = kk * 8; \
        uint32_t af[2][4]; \
        _Pragma("unroll") \
        for (int i = 0; i < 2; i++) { \
            int rb = wm * 32 + i * 16; \
            af[i][0] = Asc[(rb + g    ) * AS_STRIDE + ks + t    ]; \
            af[i][1] = Asc[(rb + g + 8) * AS_STRIDE + ks + t    ]; \
            af[i][2] = Asc[(rb + g    ) * AS_STRIDE + ks + t + 4]; \
            af[i][3] = Asc[(rb + g + 8) * AS_STRIDE + ks + t + 4]; \
        } \
        uint32_t bf[8][2]; \
        _Pragma("unroll") \
        for (int j = 0; j < 8; j++) { \
            int cb = wn * 64 + j * 8 + g; \
            bf[j][0] = Bsc[(ks + t    ) * BS_STRIDE + cb]; \
            bf[j][1] = Bsc[(ks + t + 4) * BS_STRIDE + cb]; \
        } \
        _Pragma("unroll") \
        for (int i = 0; i < 2; i++) \
            _Pragma("unroll") \
            for (int j = 0; j < 8; j++) \
                mma_tf32(acc[i][j], af[i][0], af[i][1], af[i][2], af[i][3], \
                         bf[j][0], bf[j][1]); \
    } }

#define GEMM_MAINLOOP(APTR_BASE) \
    GEMM_CPLOAD(APTR_BASE, 0, 0) \
    asm volatile("cp.async.commit_group;"); \
    _Pragma("unroll 1") \
    for (int kt = 0; kt < NT; kt++) { \
        if (kt + 1 < NT) { \
            GEMM_CPLOAD(APTR_BASE, (kt + 1) * 32, (kt + 1) & 1) \
            asm volatile("cp.async.commit_group;"); \
            asm volatile("cp.async.wait_group 1;"); \
        } else { \
            asm volatile("cp.async.wait_group 0;"); \
        } \
        __syncthreads(); \
        GEMM_COMPUTE(kt & 1) \
        __syncthreads(); \
    }

__global__ __launch_bounds__(256, 2) void qkv_gemm()
{
    GEMM_PROLOG
    int nb   = blockIdx.x;
    int wsel = nb / 6;
    const uint32_t* W = (wsel == 0) ? g_wqt : (wsel == 1 ? g_wkt : g_wvt);
    float*          O = (wsel == 0) ? g_q : (wsel == 1 ? g_k : g_v);
    int n0 = (nb % 6) * 128;
    int m0 = blockIdx.y * 128;
    const uint32_t* Abase = g_xt + (size_t)(m0 + a_row) * DIMC;

    GEMM_MAINLOOP(Abase)

#pragma unroll
    for (int i = 0; i < 2; i++) {
#pragma unroll
        for (int j = 0; j < 8; j++) {
            int r0 = m0 + wm * 32 + i * 16 + g;
            int c  = n0 + wn * 64 + j * 8 + t * 2;
            int h = c >> 6, d = c & 63;
#pragma unroll
            for (int half = 0; half < 2; half++) {
                int m = half ? r0 + 8 : r0;
                int b = m >> 12, n = m & 4095;
                float v0 = acc[i][j][half * 2 + 0];
                float v1 = acc[i][j][half * 2 + 1];
                if (wsel < 2) { v0 = fmap_f(v0); v1 = fmap_f(v1); }
                float* dst = O + (((size_t)(b * Hh + h) * Nseq + n) * Dh + d);
                dst[0] = v0; dst[1] = v1;
            }
        }
    }
}

__global__ __launch_bounds__(256, 2) void out_gemm(
    const float* __restrict__ bias, float* __restrict__ out)
{
    GEMM_PROLOG
    int n0 = blockIdx.x * 128;
    int m0 = blockIdx.y * 128;
    const uint32_t* W = g_wot;
    const uint32_t* Abase = (const uint32_t*)g_attn + (size_t)(m0 + a_row) * DIMC;

    GEMM_MAINLOOP(Abase)

#pragma unroll
    for (int i = 0; i < 2; i++) {
#pragma unroll
        for (int j = 0; j < 8; j++) {
            int r0 = m0 + wm * 32 + i * 16 + g;
            int c  = n0 + wn * 64 + j * 8 + t * 2;
            float b0 = bias[c], b1 = bias[c + 1];
            out[(size_t)r0 * DIMC + c]           = acc[i][j][0] + b0;
            out[(size_t)r0 * DIMC + c + 1]       = acc[i][j][1] + b1;
            out[(size_t)(r0 + 8) * DIMC + c]     = acc[i][j][2] + b0;
            out[(size_t)(r0 + 8) * DIMC + c + 1] = acc[i][j][3] + b1;
        }
    }
}

// =======================================================================
// MLP machinery — single tf32, permuted W layout (stride parameterized).
// =======================================================================
#define XS_STRIDE 68
#define WS_STRIDE 72       // pool kernel weight stride
#define WA_STRIDE 68       // attn kernel weight stride (tighter, fits 4 bufs)
#define POOL_SMEM_FLOATS (256 * XS_STRIDE + 64 * WS_STRIDE + 192)
#define POOL_SMEM_BYTES  (POOL_SMEM_FLOATS * 4)
// attn: X 128*68 + 4 weight bufs 64*68 + 4*192 params + 64 ksum
#define ATTN_SMEM_FLOATS (128 * XS_STRIDE + 4 * 64 * WA_STRIDE + 4 * 192 + 64)
#define ATTN_SMEM_BYTES  (ATTN_SMEM_FLOATS * 4)

__device__ __forceinline__ void load_weights_perm_s(
    uint32_t* Wd, const float* __restrict__ src, int tid, int stride, int nthr)
{
    for (int idx = tid; idx < 4096; idx += nthr) {
        int c = idx & 63;
        Wd[(idx >> 6) * stride + ((c & 7) << 3) + (c >> 3)] = f2tf32(src[idx]);
    }
}

// m32 warp tile (pool kernel, unchanged math)
__device__ __forceinline__ void mma_block64(
    float acc[2][8][4], const float* Xw, const uint32_t* Ws, int g, int t)
{
#pragma unroll
    for (int ks8 = 0; ks8 < 8; ks8++) {
        int ks = ks8 * 8;
        uint32_t af[2][4];
#pragma unroll
        for (int i = 0; i < 2; i++) {
            const float* xr = Xw + (i * 16 + g) * XS_STRIDE + ks;
            af[i][0] = f2tf32(xr[t]);
            af[i][1] = f2tf32(xr[8 * XS_STRIDE + t]);
            af[i][2] = f2tf32(xr[t + 4]);
            af[i][3] = f2tf32(xr[8 * XS_STRIDE + t + 4]);
        }
        const uint32_t* w0 = Ws + (ks + t    ) * WS_STRIDE + g * 8;
        const uint32_t* w1 = Ws + (ks + t + 4) * WS_STRIDE + g * 8;
        uint4 b0a = *(const uint4*)w0;
        uint4 b0b = *(const uint4*)(w0 + 4);
        uint4 b1a = *(const uint4*)w1;
        uint4 b1b = *(const uint4*)(w1 + 4);
        uint32_t b0[8] = {b0a.x, b0a.y, b0a.z, b0a.w, b0b.x, b0b.y, b0b.z, b0b.w};
        uint32_t b1[8] = {b1a.x, b1a.y, b1a.z, b1a.w, b1b.x, b1b.y, b1b.z, b1b.w};
#pragma unroll
        for (int j = 0; j < 8; j++)
#pragma unroll
            for (int i = 0; i < 2; i++)
                mma_tf32(acc[i][j], af[i][0], af[i][1], af[i][2], af[i][3],
                         b0[j], b1[j]);
    }
}

// m16 warp tile (attn kernel): 16 warp-private rows
__device__ __forceinline__ void mma_block64_m16(
    float acc[8][4], const float* Xw, const uint32_t* Ws, int g, int t)
{
#pragma unroll
    for (int ks8 = 0; ks8 < 8; ks8++) {
        int ks = ks8 * 8;
        const float* xr = Xw + g * XS_STRIDE + ks;
        uint32_t a0 = f2tf32(xr[t]);
        uint32_t a1 = f2tf32(xr[8 * XS_STRIDE + t]);
        uint32_t a2 = f2tf32(xr[t + 4]);
        uint32_t a3 = f2tf32(xr[8 * XS_STRIDE + t + 4]);
        const uint32_t* w0 = Ws + (ks + t    ) * WA_STRIDE + g * 8;
        const uint32_t* w1 = Ws + (ks + t + 4) * WA_STRIDE + g * 8;
        uint4 b0a = *(const uint4*)w0;
        uint4 b0b = *(const uint4*)(w0 + 4);
        uint4 b1a = *(const uint4*)w1;
        uint4 b1b = *(const uint4*)(w1 + 4);
        uint32_t b0[8] = {b0a.x, b0a.y, b0a.z, b0a.w, b0b.x, b0b.y, b0b.z, b0b.w};
        uint32_t b1[8] = {b1a.x, b1a.y, b1a.z, b1a.w, b1b.x, b1b.y, b1b.z, b1b.w};
#pragma unroll
        for (int j = 0; j < 8; j++)
            mma_tf32(acc[j], a0, a1, a2, a3, b0[j], b1[j]);
    }
}

__device__ __forceinline__ void ln_gelu_regs(
    float acc[2][8][4], const float* Pb, const float* Pg, const float* Pe, int t)
{
#pragma unroll
    for (int i = 0; i < 2; i++) {
        float s1A = 0, s2A = 0, s1B = 0, s2B = 0;
#pragma unroll
        for (int j = 0; j < 8; j++) {
#pragma unroll
            for (int q = 0; q < 4; q++) {
                int col = j * 8 + t * 2 + (q & 1);
                float v = acc[i][j][q] + Pb[col];
                acc[i][j][q] = v;
                if (q < 2) { s1A += v; s2A += v * v; }
                else       { s1B += v; s2B += v * v; }
            }
        }
        s1A += __shfl_xor_sync(~0u, s1A, 1); s2A += __shfl_xor_sync(~0u, s2A, 1);
        s1B += __shfl_xor_sync(~0u, s1B, 1); s2B += __shfl_xor_sync(~0u, s2B, 1);
        s1A += __shfl_xor_sync(~0u, s1A, 2); s2A += __shfl_xor_sync(~0u, s2A, 2);
        s1B += __shfl_xor_sync(~0u, s1B, 2); s2B += __shfl_xor_sync(~0u, s2B, 2);
        float muA = s1A * (1.0f / 64.0f);
        float muB = s1B * (1.0f / 64.0f);
        float rA = rsqrtf(s2A * (1.0f / 64.0f) - muA * muA + 1e-5f);
        float rB = rsqrtf(s2B * (1.0f / 64.0f) - muB * muB + 1e-5f);
#pragma unroll
        for (int j = 0; j < 8; j++) {
#pragma unroll
            for (int q = 0; q < 4; q++) {
                int col = j * 8 + t * 2 + (q & 1);
                float mu = (q < 2) ? muA : muB;
                float rv = (q < 2) ? rA : rB;
                acc[i][j][q] = gelu_f((acc[i][j][q] - mu) * rv * Pg[col] + Pe[col]);
            }
        }
    }
}

// m16 variant
__device__ __forceinline__ void ln_gelu_regs_m16(
    float acc[8][4], const float* Pb, const float* Pg, const float* Pe, int t)
{
    float s1A = 0, s2A = 0, s1B = 0, s2B = 0;
#pragma unroll
    for (int j = 0; j < 8; j++) {
#pragma unroll
        for (int q = 0; q < 4; q++) {
            int col = j * 8 + t * 2 + (q & 1);
            float v = acc[j][q] + Pb[col];
            acc[j][q] = v;
            if (q < 2) { s1A += v; s2A += v * v; }
            else       { s1B += v; s2B += v * v; }
        }
    }
    s1A += __shfl_xor_sync(~0u, s1A, 1); s2A += __shfl_xor_sync(~0u, s2A, 1);
    s1B += __shfl_xor_sync(~0u, s1B, 1); s2B += __shfl_xor_sync(~0u, s2B, 1);
    s1A += __shfl_xor_sync(~0u, s1A, 2); s2A += __shfl_xor_sync(~0u, s2A, 2);
    s1B += __shfl_xor_sync(~0u, s1B, 2); s2B += __shfl_xor_sync(~0u, s2B, 2);
    float muA = s1A * (1.0f / 64.0f);
    float muB = s1B * (1.0f / 64.0f);
    float rA = rsqrtf(s2A * (1.0f / 64.0f) - muA * muA + 1e-5f);
    float rB = rsqrtf(s2B * (1.0f / 64.0f) - muB * muB + 1e-5f);
#pragma unroll
    for (int j = 0; j < 8; j++) {
#pragma unroll
        for (int q = 0; q < 4; q++) {
            int col = j * 8 + t * 2 + (q & 1);
            float mu = (q < 2) ? muA : muB;
            float rv = (q < 2) ? rA : rB;
            acc[j][q] = gelu_f((acc[j][q] - mu) * rv * Pg[col] + Pe[col]);
        }
    }
}

// ---------------- pool stage (tensor core): pair-mean + MLP(LN+gelu) --------
__global__ __launch_bounds__(256, 2) void pool_mlp_tc(
    int stage,
    const float* __restrict__ pW, const float* __restrict__ pb,
    const float* __restrict__ pg, const float* __restrict__ pbe)
{
    extern __shared__ float sm[];
    float*    Xs = sm;
    uint32_t* Ws = (uint32_t*)(sm + 256 * XS_STRIDE);
    float*    Pb = (float*)(Ws + 64 * WS_STRIDE);
    float*    Pg = Pb + 64;
    float*    Pe = Pg + 64;

    const float* in; float* out; int s_in, s_out;
    if (stage == 0)      { in = g_k;   out = g_kcA; s_in = 4096; s_out = 2048; }
    else if (stage == 1) { in = g_kcA; out = g_kcB; s_in = 2048; s_out = 1024; }
    else                 { in = g_kcB; out = g_kcA; s_in = 1024; s_out = 512;  }

    int tid = threadIdx.x, warp = tid >> 5, lane = tid & 31;
    int g = lane >> 2, t = lane & 3;

    for (int idx = tid; idx < 256 * 16; idx += 256) {
        int r = idx >> 4, c4 = (idx & 15) << 2;
        int rg = blockIdx.x * 256 + r;
        int bh = rg / s_out, n = rg - bh * s_out;
        const float* src = in + ((size_t)bh * s_in + 2 * n) * 64 + c4;
        float4 a = *(const float4*)src;
        float4 b = *(const float4*)(src + 64);
        float4 v;
        v.x = 0.5f * (a.x + b.x); v.y = 0.5f * (a.y + b.y);
        v.z = 0.5f * (a.z + b.z); v.w = 0.5f * (a.w + b.w);
        *(float4*)&Xs[r * XS_STRIDE + c4] = v;
    }
    load_weights_perm_s(Ws, pW + stage * 4096, tid, WS_STRIDE, 256);
    if (tid < 64) {
        Pb[tid] = pb[stage * 64 + tid];
        Pg[tid] = pg[stage * 64 + tid];
        Pe[tid] = pbe[stage * 64 + tid];
    }
    __syncthreads();

    float acc[2][8][4];
#pragma unroll
    for (int i = 0; i < 2; i++)
#pragma unroll
        for (int j = 0; j < 8; j++)
#pragma unroll
            for (int q = 0; q < 4; q++) acc[i][j][q] = 0.0f;

    mma_block64(acc, Xs + warp * 32 * XS_STRIDE, Ws, g, t);
    ln_gelu_regs(acc, Pb, Pg, Pe, t);

    float* ob = out + (size_t)(blockIdx.x * 256 + warp * 32) * 64;
#pragma unroll
    for (int i = 0; i < 2; i++) {
#pragma unroll
        for (int j = 0; j < 8; j++) {
            int col = j * 8 + t * 2;
            float2 v0 = make_float2(acc[i][j][0], acc[i][j][1]);
            float2 v1 = make_float2(acc[i][j][2], acc[i][j][3]);
            *(float2*)(ob + (i * 16 + g    ) * 64 + col) = v0;
            *(float2*)(ob + (i * 16 + g + 8) * 64 + col) = v1;
        }
    }
}

// ---------------- fused attention apply + 3 exp MLP stages ------------------
// Barrier-free mainchain: ALL weights loaded up front (kv + 3 stages), one
// __syncthreads(), then each warp runs the 4-stage chain on its private
// 16 rows with only __syncwarp() between stages.
__global__ __launch_bounds__(256, 2) void attn_mlp_tc(
    const float* __restrict__ eW, const float* __restrict__ eb,
    const float* __restrict__ eg, const float* __restrict__ ebe)
{
    extern __shared__ float sm[];
    float*    Xs  = sm;                                     // 128 x 68
    uint32_t* W4  = (uint32_t*)(sm + 128 * XS_STRIDE);      // 4 x 64 x 68
    float*    P4  = (float*)(W4 + 4 * 64 * WA_STRIDE);      // 4 x 192
    float*    Ksm = P4 + 4 * 192;

    int tid = threadIdx.x, warp = tid >> 5, lane = tid & 31;
    int g = lane >> 2, t = lane & 3;
    int bh = blockIdx.x >> 5;
    int n0 = (blockIdx.x & 31) << 7;      // 128 rows per block

    const float* qb = g_q + ((size_t)bh * 4096 + n0) * 64;
    for (int idx = tid; idx < 128 * 16; idx += 256) {
        int r = idx >> 4, c4 = (idx & 15) << 2;
        *(float4*)&Xs[r * XS_STRIDE + c4] = *(const float4*)(qb + r * 64 + c4);
    }
    // weight buffers: [0]=kv, [1]=eW2, [2]=eW1, [3]=eW0
    load_weights_perm_s(W4,                    g_kv + bh * 4096, tid, WA_STRIDE, 256);
    load_weights_perm_s(W4 + 1 * 64 * WA_STRIDE, eW + 2 * 4096,  tid, WA_STRIDE, 256);
    load_weights_perm_s(W4 + 2 * 64 * WA_STRIDE, eW + 1 * 4096,  tid, WA_STRIDE, 256);
    load_weights_perm_s(W4 + 3 * 64 * WA_STRIDE, eW + 0 * 4096,  tid, WA_STRIDE, 256);
    if (tid < 64) {
        Ksm[tid] = g_ksum[bh * 64 + tid];
#pragma unroll
        for (int s = 0; s < 3; s++) {
            float* Pd = P4 + (s + 1) * 192;        // buf s+1 holds stage (2-s)
            int src = 2 - s;
            Pd[tid]       = eb[src * 64 + tid];
            Pd[64 + tid]  = eg[src * 64 + tid];
            Pd[128 + tid] = ebe[src * 64 + tid];
        }
    }
    __syncthreads();   // the ONLY block-wide barrier

    float* Xw = Xs + warp * 16 * XS_STRIDE;   // warp-private 16 rows

    float acc[8][4];
#pragma unroll
    for (int j = 0; j < 8; j++)
#pragma unroll
        for (int q = 0; q < 4; q++) acc[j][q] = 0.0f;

    // stage 0: y = q @ kv
    mma_block64_m16(acc, Xw, W4, g, t);

    // per-row inv = 1/(q.ksum + 1e-6) for rows g and g+8
    float invA, invB;
    {
        const float* xr = Xw + g * XS_STRIDE;
        float dp = 0.0f;
#pragma unroll
        for (int e = 0; e < 16; e++) dp += xr[t + e * 4] * Ksm[t + e * 4];
        dp += __shfl_xor_sync(~0u, dp, 1);
        dp += __shfl_xor_sync(~0u, dp, 2);
        invA = 1.0f / (dp + 1e-6f);
        const float* xr2 = Xw + (g + 8) * XS_STRIDE;
        float dp2 = 0.0f;
#pragma unroll
        for (int e = 0; e < 16; e++) dp2 += xr2[t + e * 4] * Ksm[t + e * 4];
        dp2 += __shfl_xor_sync(~0u, dp2, 1);
        dp2 += __shfl_xor_sync(~0u, dp2, 2);
        invB = 1.0f / (dp2 + 1e-6f);
    }
    __syncwarp();   // all lanes done reading Xw (q) before overwrite
#pragma unroll
    for (int j = 0; j < 8; j++) {
        int col = j * 8 + t * 2;
        *(float2*)&Xw[g * XS_STRIDE + col] =
            make_float2(acc[j][0] * invA, acc[j][1] * invA);
        *(float2*)&Xw[(g + 8) * XS_STRIDE + col] =
            make_float2(acc[j][2] * invB, acc[j][3] * invB);
    }
    __syncwarp();

    int b = bh / Hh, h = bh - b * Hh;
    float* obase = g_attn + ((size_t)b * 4096 + n0 + warp * 16) * DIMC + h * 64;

#pragma unroll
    for (int sb = 1; sb <= 3; sb++) {      // buffers 1,2,3 = exp stages 2,1,0
#pragma unroll
        for (int j = 0; j < 8; j++)
#pragma unroll
            for (int q = 0; q < 4; q++) acc[j][q] = 0.0f;

        mma_block64_m16(acc, Xw, W4 + sb * 64 * WA_STRIDE, g, t);
        const float* Pd = P4 + sb * 192;
        ln_gelu_regs_m16(acc, Pd, Pd + 64, Pd + 128, t);

        if (sb < 3) {
            __syncwarp();
#pragma unroll
            for (int j = 0; j < 8; j++) {
                int col = j * 8 + t * 2;
                *(float2*)&Xw[g * XS_STRIDE + col] =
                    make_float2(acc[j][0], acc[j][1]);
                *(float2*)&Xw[(g + 8) * XS_STRIDE + col] =
                    make_float2(acc[j][2], acc[j][3]);
            }
            __syncwarp();
        } else {
            // final: store tf32 bit-patterns for out_gemm
#pragma unroll
            for (int j = 0; j < 8; j++) {
                int col = j * 8 + t * 2;
                *(float2*)(obase + (size_t)g * DIMC + col) =
                    make_float2(__uint_as_float(f2tf32(acc[j][0])),
                                __uint_as_float(f2tf32(acc[j][1])));
                *(float2*)(obase + (size_t)(g + 8) * DIMC + col) =
                    make_float2(__uint_as_float(f2tf32(acc[j][2])),
                                __uint_as_float(f2tf32(acc[j][3])));
            }
        }
    }
}

// ---------------- vc pooling: mean over 8 consecutive tokens ----------------
__global__ void vpool_kernel()
{
    int idx = blockIdx.x * 256 + threadIdx.x;
    if (idx >= BH * 512 * Dh) return;
    int d   = idx & 63;
    int rest = idx >> 6;
    int n   = rest & 511;
    int bh  = rest >> 9;
    const float* src = g_v + (bh * 4096 + n * 8) * 64 + d;
    float s = 0.0f;
#pragma unroll
    for (int j = 0; j < 8; j++) s += src[j * 64];
    g_vc[idx] = s * 0.125f;
}

// ---------------- kv = (kc/sqrt(512))^T vc, plus k_sum, per (b,h) -----------
__global__ __launch_bounds__(256) void kv_kernel()
{
    int bh = blockIdx.x;
    __shared__ float ks[64][65];
    __shared__ float vs[64][65];
    int tid = threadIdx.x;
    int td = tid & 15, te = tid >> 4;
    float acc[4][4];
#pragma unroll
    for (int i = 0; i < 4; i++)
#pragma unroll
        for (int j = 0; j < 4; j++) acc[i][j] = 0.0f;
    float colsum = 0.0f;
    const float scale = rsqrtf(512.0f);

    for (int nt = 0; nt < 512; nt += 64) {
        for (int i = tid; i < 4096; i += 256) {
            int rr = i >> 6, cc = i & 63;
            ks[rr][cc] = g_kcA[(bh * 512 + nt + rr) * 64 + cc] * scale;
            vs[rr][cc] = g_vc [(bh * 512 + nt + rr) * 64 + cc];
        }
        __syncthreads();
        if (tid < 64) {
            for (int rr = 0; rr < 64; rr++) colsum += ks[rr][tid];
        }
#pragma unroll 4
        for (int nn = 0; nn < 64; nn++) {
            float a[4], bb[4];
#pragma unroll
            for (int i = 0; i < 4; i++) a[i]  = ks[nn][td * 4 + i];
#pragma unroll
            for (int j = 0; j < 4; j++) bb[j] = vs[nn][te * 4 + j];
#pragma unroll
            for (int i = 0; i < 4; i++)
#pragma unroll
                for (int j = 0; j < 4; j++)
                    acc[i][j] = fmaf(a[i], bb[j], acc[i][j]);
        }
        __syncthreads();
    }
#pragma unroll
    for (int i = 0; i < 4; i++)
#pragma unroll
        for (int j = 0; j < 4; j++)
            g_kv[(bh * 64 + td * 4 + i) * 64 + te * 4 + j] = acc[i][j];
    if (tid < 64) g_ksum[bh * 64 + tid] = colsum;
}

// ---------------- launch --------------------------------------------------
extern "C" void kernel_launch(void* const* d_in, const int* in_sizes, int n_in,
                              void* d_out, int out_size)
{
    const float* x   = (const float*)d_in[0];
    const float* Wq  = (const float*)d_in[1];
    const float* Wk  = (const float*)d_in[2];
    const float* Wv  = (const float*)d_in[3];
    const float* pW  = (const float*)d_in[4];
    const float* pb  = (const float*)d_in[5];
    const float* pg  = (const float*)d_in[6];
    const float* pbe = (const float*)d_in[7];
    const float* eW  = (const float*)d_in[8];
    const float* eb  = (const float*)d_in[9];
    const float* eg  = (const float*)d_in[10];
    const float* ebe = (const float*)d_in[11];
    const float* Wo  = (const float*)d_in[12];
    const float* bo  = (const float*)d_in[13];
    float* out = (float*)d_out;

    cudaFuncSetAttribute(qkv_gemm,
        cudaFuncAttributeMaxDynamicSharedMemorySize, GEMM_SMEM_BYTES);
    cudaFuncSetAttribute(out_gemm,
        cudaFuncAttributeMaxDynamicSharedMemorySize, GEMM_SMEM_BYTES);
    cudaFuncSetAttribute(pool_mlp_tc,
        cudaFuncAttributeMaxDynamicSharedMemorySize, POOL_SMEM_BYTES);
    cudaFuncSetAttribute(attn_mlp_tc,
        cudaFuncAttributeMaxDynamicSharedMemorySize, ATTN_SMEM_BYTES);

    prep_x<<<(MR * DIMC / 4 + 255) / 256, 256>>>((const float4*)x);
    prep_w<<<(4 * DIMC * DIMC / 4 + 255) / 256, 256>>>(
        (const float4*)Wq, (const float4*)Wk, (const float4*)Wv, (const float4*)Wo);

    qkv_gemm<<<dim3(18, MR / 128), 256, GEMM_SMEM_BYTES>>>();
    vpool_kernel<<<(BH * 512 * Dh + 255) / 256, 256>>>();
    pool_mlp_tc<<<BH * 2048 / 256, 256, POOL_SMEM_BYTES>>>(0, pW, pb, pg, pbe);
    pool_mlp_tc<<<BH * 1024 / 256, 256, POOL_SMEM_BYTES>>>(1, pW, pb, pg, pbe);
    pool_mlp_tc<<<BH * 512 / 256, 256, POOL_SMEM_BYTES>>>(2, pW, pb, pg, pbe);
    kv_kernel<<<BH, 256>>>();
    attn_mlp_tc<<<BH * 32, 256, ATTN_SMEM_BYTES>>>(eW, eb, eg, ebe);
    out_gemm<<<dim3(6, MR / 128), 256, GEMM_SMEM_BYTES>>>(bo, out);
}

// round 14
// speedup vs baseline: 1.0650x; 1.0650x over previous
#include <cuda_runtime.h>
#include <math.h>
#include <stdint.h>

#define Bz   8
#define Nseq 4096
#define DIMC 768
#define Hh   12
#define Dh   64
#define BH   (Bz*Hh)        // 96
#define MR   (Bz*Nseq)      // 32768

// ---------------- scratch (device globals; no allocations allowed) ----------
__device__ float g_q[BH*Nseq*Dh];
__device__ float g_k[BH*Nseq*Dh];
__device__ float g_v[BH*Nseq*Dh];
__device__ float g_kcA[BH*2048*Dh];
__device__ float g_kcB[BH*1024*Dh];
__device__ float g_vc[BH*512*Dh];
__device__ float g_ksum[BH*Dh];
__device__ float g_attn[MR*DIMC];          // holds tf32 bit-patterns (as float)
__device__ uint32_t g_xt[MR*DIMC];         // X pre-converted to tf32 bits
__device__ uint32_t g_wqt[DIMC*DIMC];
__device__ uint32_t g_wkt[DIMC*DIMC];
__device__ uint32_t g_wvt[DIMC*DIMC];
__device__ uint32_t g_wot[DIMC*DIMC];
__device__ uint32_t g_kvt[BH*Dh*Dh];       // kv, permuted tf32 layout
__device__ uint32_t g_ewt[3*Dh*Dh];        // exp weights, permuted tf32
__device__ uint32_t g_pwt[3*Dh*Dh];        // pool weights, permuted tf32

__device__ __forceinline__ float gelu_f(float t) {
    return 0.5f * t * (1.0f + erff(t * 0.70710678118654752f));
}
__device__ __forceinline__ float fmap_f(float t) {   // elu(t)+1
    return t > 0.0f ? t + 1.0f : expf(t);
}
__device__ __forceinline__ uint32_t f2tf32(float f) {
    uint32_t r;
    asm("cvt.rna.tf32.f32 %0, %1;" : "=r"(r) : "f"(f));
    return r;
}
__device__ __forceinline__ void mma_tf32(float c[4],
    uint32_t a0, uint32_t a1, uint32_t a2, uint32_t a3,
    uint32_t b0, uint32_t b1)
{
    asm volatile(
        "mma.sync.aligned.m16n8k8.row.col.f32.tf32.tf32.f32 "
        "{%0,%1,%2,%3}, {%4,%5,%6,%7}, {%8,%9}, {%0,%1,%2,%3};"
        : "+f"(c[0]), "+f"(c[1]), "+f"(c[2]), "+f"(c[3])
        : "r"(a0), "r"(a1), "r"(a2), "r"(a3), "r"(b0), "r"(b1));
}
__device__ __forceinline__ void cp_async16(uint32_t dst, const void* src) {
    asm volatile("cp.async.cg.shared.global [%0], [%1], 16;" :: "r"(dst), "l"(src));
}

// ---------------- prepasses: fp32 -> tf32 bit patterns ----------------------
__global__ void prep_x(const float4* __restrict__ src)
{
    int i = blockIdx.x * 256 + threadIdx.x;
    if (i < MR * DIMC / 4) {
        float4 v = src[i];
        uint4 o;
        o.x = f2tf32(v.x); o.y = f2tf32(v.y);
        o.z = f2tf32(v.z); o.w = f2tf32(v.w);
        ((uint4*)g_xt)[i] = o;
    }
}
__global__ void prep_w(const float4* __restrict__ wq, const float4* __restrict__ wk,
                       const float4* __restrict__ wv, const float4* __restrict__ wo)
{
    const int n4 = DIMC * DIMC / 4;
    int i = blockIdx.x * 256 + threadIdx.x;
    if (i >= 4 * n4) return;
    int seg = i / n4, r = i - seg * n4;
    const float4* s = (seg == 0) ? wq : (seg == 1) ? wk : (seg == 2) ? wv : wo;
    uint4* d = (seg == 0) ? (uint4*)g_wqt : (seg == 1) ? (uint4*)g_wkt
             : (seg == 2) ? (uint4*)g_wvt : (uint4*)g_wot;
    float4 v = s[r];
    uint4 o;
    o.x = f2tf32(v.x); o.y = f2tf32(v.y);
    o.z = f2tf32(v.z); o.w = f2tf32(v.w);
    d[r] = o;
}
// small weights (eW, pW) -> permuted tf32 dense arrays
__global__ void prep_small(const float* __restrict__ eW, const float* __restrict__ pW)
{
    int i = blockIdx.x * 256 + threadIdx.x;
    if (i >= 2 * 3 * 4096) return;
    int which = i / (3 * 4096);
    int rem   = i - which * (3 * 4096);
    const float* src = which ? pW : eW;
    uint32_t*    dst = which ? g_pwt : g_ewt;
    int rc = rem & 4095;
    int c = rc & 63;
    dst[(rem & ~4095) + (rc & ~63) + ((c & 7) << 3) + (c >> 3)] = f2tf32(src[rem]);
}

// =======================================================================
// Big GEMMs: tf32, cp.async double-buffered for BOTH A and B.
// =======================================================================
#define AS_STRIDE 36
#define BS_STRIDE 136
#define AS_TILE   (128 * AS_STRIDE)
#define BS_TILE   (32 * BS_STRIDE)
#define NT        (DIMC / 32)
#define GEMM_SMEM_BYTES ((2 * AS_TILE + 2 * BS_TILE) * 4)

#define GEMM_PROLOG \
    extern __shared__ uint32_t smemg[]; \
    uint32_t* Asf = smemg; \
    uint32_t* Bsf = smemg + 2 * AS_TILE; \
    uint32_t As_base = (uint32_t)__cvta_generic_to_shared(Asf); \
    uint32_t Bs_base = (uint32_t)__cvta_generic_to_shared(Bsf); \
    int tid = threadIdx.x; \
    int warp = tid >> 5, lane = tid & 31; \
    int g = lane >> 2, t = lane & 3; \
    int wm = warp >> 1, wn = warp & 1; \
    int a_row = tid >> 1, a_col = (tid & 1) << 4; \
    int b_row = tid >> 3, b_col = (tid & 7) << 4; \
    float acc[2][8][4]; \
    _Pragma("unroll") \
    for (int i = 0; i < 2; i++) \
        _Pragma("unroll") \
        for (int j = 0; j < 8; j++) \
            _Pragma("unroll") \
            for (int q = 0; q < 4; q++) acc[i][j][q] = 0.0f;

#define GEMM_CPLOAD(APTR_BASE, K0, BUF) { \
    const uint32_t* ap_ = (APTR_BASE) + (K0) + a_col; \
    const uint32_t* bp_ = W + (size_t)((K0) + b_row) * DIMC + n0 + b_col; \
    uint32_t asd = As_base + (uint32_t)(((BUF) * AS_TILE + a_row * AS_STRIDE + a_col) * 4); \
    uint32_t bsd = Bs_base + (uint32_t)(((BUF) * BS_TILE + b_row * BS_STRIDE + b_col) * 4); \
    _Pragma("unroll") \
    for (int u = 0; u < 4; u++) { \
        cp_async16(asd + u * 16, ap_ + u * 4); \
        cp_async16(bsd + u * 16, bp_ + u * 4); \
    } }

#define GEMM_COMPUTE(BUF) { \
    const uint32_t* Asc = Asf + (BUF) * AS_TILE; \
    const uint32_t* Bsc = Bsf + (BUF) * BS_TILE; \
    _Pragma("unroll") \
    for (int kk = 0; kk < 4; kk++) { \
        int ks = kk * 8; \
        uint32_t af[2][4]; \
        _Pragma("unroll") \
        for (int i = 0; i < 2; i++) { \
            int rb = wm * 32 + i * 16; \
            af[i][0] = Asc[(rb + g    ) * AS_STRIDE + ks + t    ]; \
            af[i][1] = Asc[(rb + g + 8) * AS_STRIDE + ks + t    ]; \
            af[i][2] = Asc[(rb + g    ) * AS_STRIDE + ks + t + 4]; \
            af[i][3] = Asc[(rb + g + 8) * AS_STRIDE + ks + t + 4]; \
        } \
        uint32_t bf[8][2]; \
        _Pragma("unroll") \
        for (int j = 0; j < 8; j++) { \
            int cb = wn * 64 + j * 8 + g; \
            bf[j][0] = Bsc[(ks + t    ) * BS_STRIDE + cb]; \
            bf[j][1] = Bsc[(ks + t + 4) * BS_STRIDE + cb]; \
        } \
        _Pragma("unroll") \
        for (int i = 0; i < 2; i++) \
            _Pragma("unroll") \
            for (int j = 0; j < 8; j++) \
                mma_tf32(acc[i][j], af[i][0], af[i][1], af[i][2], af[i][3], \
                         bf[j][0], bf[j][1]); \
    } }

#define GEMM_MAINLOOP(APTR_BASE) \
    GEMM_CPLOAD(APTR_BASE, 0, 0) \
    asm volatile("cp.async.commit_group;"); \
    _Pragma("unroll 1") \
    for (int kt = 0; kt < NT; kt++) { \
        if (kt + 1 < NT) { \
            GEMM_CPLOAD(APTR_BASE, (kt + 1) * 32, (kt + 1) & 1) \
            asm volatile("cp.async.commit_group;"); \
            asm volatile("cp.async.wait_group 1;"); \
        } else { \
            asm volatile("cp.async.wait_group 0;"); \
        } \
        __syncthreads(); \
        GEMM_COMPUTE(kt & 1) \
        __syncthreads(); \
    }

__global__ __launch_bounds__(256, 2) void qkv_gemm()
{
    GEMM_PROLOG
    int nb   = blockIdx.x;
    int wsel = nb / 6;
    const uint32_t* W = (wsel == 0) ? g_wqt : (wsel == 1 ? g_wkt : g_wvt);
    float*          O = (wsel == 0) ? g_q : (wsel == 1 ? g_k : g_v);
    int n0 = (nb % 6) * 128;
    int m0 = blockIdx.y * 128;
    const uint32_t* Abase = g_xt + (size_t)(m0 + a_row) * DIMC;

    GEMM_MAINLOOP(Abase)

#pragma unroll
    for (int i = 0; i < 2; i++) {
#pragma unroll
        for (int j = 0; j < 8; j++) {
            int r0 = m0 + wm * 32 + i * 16 + g;
            int c  = n0 + wn * 64 + j * 8 + t * 2;
            int h = c >> 6, d = c & 63;
#pragma unroll
            for (int half = 0; half < 2; half++) {
                int m = half ? r0 + 8 : r0;
                int b = m >> 12, n = m & 4095;
                float v0 = acc[i][j][half * 2 + 0];
                float v1 = acc[i][j][half * 2 + 1];
                if (wsel < 2) { v0 = fmap_f(v0); v1 = fmap_f(v1); }
                float* dst = O + (((size_t)(b * Hh + h) * Nseq + n) * Dh + d);
                dst[0] = v0; dst[1] = v1;
            }
        }
    }
}

__global__ __launch_bounds__(256, 2) void out_gemm(
    const float* __restrict__ bias, float* __restrict__ out)
{
    GEMM_PROLOG
    int n0 = blockIdx.x * 128;
    int m0 = blockIdx.y * 128;
    const uint32_t* W = g_wot;
    const uint32_t* Abase = (const uint32_t*)g_attn + (size_t)(m0 + a_row) * DIMC;

    GEMM_MAINLOOP(Abase)

#pragma unroll
    for (int i = 0; i < 2; i++) {
#pragma unroll
        for (int j = 0; j < 8; j++) {
            int r0 = m0 + wm * 32 + i * 16 + g;
            int c  = n0 + wn * 64 + j * 8 + t * 2;
            float b0 = bias[c], b1 = bias[c + 1];
            out[(size_t)r0 * DIMC + c]           = acc[i][j][0] + b0;
            out[(size_t)r0 * DIMC + c + 1]       = acc[i][j][1] + b1;
            out[(size_t)(r0 + 8) * DIMC + c]     = acc[i][j][2] + b0;
            out[(size_t)(r0 + 8) * DIMC + c + 1] = acc[i][j][3] + b1;
        }
    }
}

// =======================================================================
// Tensor-core 64-wide MLP machinery — single tf32, permuted W layout.
// Weights are pre-permuted+converted in GLOBAL; loaders are uint4 copies.
// =======================================================================
#define XS_STRIDE 68
#define WS_STRIDE 72
#define POOL_SMEM_FLOATS (256 * XS_STRIDE + 64 * WS_STRIDE + 192)
#define POOL_SMEM_BYTES  (POOL_SMEM_FLOATS * 4)
#define ATTN_SMEM_FLOATS (256 * XS_STRIDE + 2 * 64 * WS_STRIDE + 2 * 192 + 64)
#define ATTN_SMEM_BYTES  (ATTN_SMEM_FLOATS * 4)

// vectorized copy of a pre-permuted 64x64 weight tile into smem (stride rows)
__device__ __forceinline__ void copy_w_smem(
    uint32_t* Wd, const uint32_t* __restrict__ src, int tid)
{
    for (int idx = tid * 4; idx < 4096; idx += 1024) {
        uint4 v = *(const uint4*)(src + idx);
        *(uint4*)(Wd + (idx >> 6) * WS_STRIDE + (idx & 63)) = v;
    }
}

__device__ __forceinline__ void mma_block64(
    float acc[2][8][4], const float* Xw, const uint32_t* Ws, int g, int t)
{
#pragma unroll
    for (int ks8 = 0; ks8 < 8; ks8++) {
        int ks = ks8 * 8;
        uint32_t af[2][4];
#pragma unroll
        for (int i = 0; i < 2; i++) {
            const float* xr = Xw + (i * 16 + g) * XS_STRIDE + ks;
            af[i][0] = f2tf32(xr[t]);
            af[i][1] = f2tf32(xr[8 * XS_STRIDE + t]);
            af[i][2] = f2tf32(xr[t + 4]);
            af[i][3] = f2tf32(xr[8 * XS_STRIDE + t + 4]);
        }
        const uint32_t* w0 = Ws + (ks + t    ) * WS_STRIDE + g * 8;
        const uint32_t* w1 = Ws + (ks + t + 4) * WS_STRIDE + g * 8;
        uint4 b0a = *(const uint4*)w0;
        uint4 b0b = *(const uint4*)(w0 + 4);
        uint4 b1a = *(const uint4*)w1;
        uint4 b1b = *(const uint4*)(w1 + 4);
        uint32_t b0[8] = {b0a.x, b0a.y, b0a.z, b0a.w, b0b.x, b0b.y, b0b.z, b0b.w};
        uint32_t b1[8] = {b1a.x, b1a.y, b1a.z, b1a.w, b1b.x, b1b.y, b1b.z, b1b.w};
#pragma unroll
        for (int j = 0; j < 8; j++)
#pragma unroll
            for (int i = 0; i < 2; i++)
                mma_tf32(acc[i][j], af[i][0], af[i][1], af[i][2], af[i][3],
                         b0[j], b1[j]);
    }
}

__device__ __forceinline__ void ln_gelu_regs(
    float acc[2][8][4], const float* Pb, const float* Pg, const float* Pe, int t)
{
#pragma unroll
    for (int i = 0; i < 2; i++) {
        float s1A = 0, s2A = 0, s1B = 0, s2B = 0;
#pragma unroll
        for (int j = 0; j < 8; j++) {
#pragma unroll
            for (int q = 0; q < 4; q++) {
                int col = j * 8 + t * 2 + (q & 1);
                float v = acc[i][j][q] + Pb[col];
                acc[i][j][q] = v;
                if (q < 2) { s1A += v; s2A += v * v; }
                else       { s1B += v; s2B += v * v; }
            }
        }
        s1A += __shfl_xor_sync(~0u, s1A, 1); s2A += __shfl_xor_sync(~0u, s2A, 1);
        s1B += __shfl_xor_sync(~0u, s1B, 1); s2B += __shfl_xor_sync(~0u, s2B, 1);
        s1A += __shfl_xor_sync(~0u, s1A, 2); s2A += __shfl_xor_sync(~0u, s2A, 2);
        s1B += __shfl_xor_sync(~0u, s1B, 2); s2B += __shfl_xor_sync(~0u, s2B, 2);
        float muA = s1A * (1.0f / 64.0f);
        float muB = s1B * (1.0f / 64.0f);
        float rA = rsqrtf(s2A * (1.0f / 64.0f) - muA * muA + 1e-5f);
        float rB = rsqrtf(s2B * (1.0f / 64.0f) - muB * muB + 1e-5f);
#pragma unroll
        for (int j = 0; j < 8; j++) {
#pragma unroll
            for (int q = 0; q < 4; q++) {
                int col = j * 8 + t * 2 + (q & 1);
                float mu = (q < 2) ? muA : muB;
                float rv = (q < 2) ? rA : rB;
                acc[i][j][q] = gelu_f((acc[i][j][q] - mu) * rv * Pg[col] + Pe[col]);
            }
        }
    }
}

// ---------------- pool stage (tensor core): pair-mean + MLP(LN+gelu) --------
__global__ __launch_bounds__(256, 2) void pool_mlp_tc(
    int stage,
    const float* __restrict__ pb,
    const float* __restrict__ pg, const float* __restrict__ pbe)
{
    extern __shared__ float sm[];
    float*    Xs = sm;
    uint32_t* Ws = (uint32_t*)(sm + 256 * XS_STRIDE);
    float*    Pb = (float*)(Ws + 64 * WS_STRIDE);
    float*    Pg = Pb + 64;
    float*    Pe = Pg + 64;

    const float* in; float* out; int s_in, s_out;
    if (stage == 0)      { in = g_k;   out = g_kcA; s_in = 4096; s_out = 2048; }
    else if (stage == 1) { in = g_kcA; out = g_kcB; s_in = 2048; s_out = 1024; }
    else                 { in = g_kcB; out = g_kcA; s_in = 1024; s_out = 512;  }

    int tid = threadIdx.x, warp = tid >> 5, lane = tid & 31;
    int g = lane >> 2, t = lane & 3;

    for (int idx = tid; idx < 256 * 16; idx += 256) {
        int r = idx >> 4, c4 = (idx & 15) << 2;
        int rg = blockIdx.x * 256 + r;
        int bh = rg / s_out, n = rg - bh * s_out;
        const float* src = in + ((size_t)bh * s_in + 2 * n) * 64 + c4;
        float4 a = *(const float4*)src;
        float4 b = *(const float4*)(src + 64);
        float4 v;
        v.x = 0.5f * (a.x + b.x); v.y = 0.5f * (a.y + b.y);
        v.z = 0.5f * (a.z + b.z); v.w = 0.5f * (a.w + b.w);
        *(float4*)&Xs[r * XS_STRIDE + c4] = v;
    }
    copy_w_smem(Ws, g_pwt + stage * 4096, tid);
    if (tid < 64) {
        Pb[tid] = pb[stage * 64 + tid];
        Pg[tid] = pg[stage * 64 + tid];
        Pe[tid] = pbe[stage * 64 + tid];
    }
    __syncthreads();

    float acc[2][8][4];
#pragma unroll
    for (int i = 0; i < 2; i++)
#pragma unroll
        for (int j = 0; j < 8; j++)
#pragma unroll
            for (int q = 0; q < 4; q++) acc[i][j][q] = 0.0f;

    mma_block64(acc, Xs + warp * 32 * XS_STRIDE, Ws, g, t);
    ln_gelu_regs(acc, Pb, Pg, Pe, t);

    float* ob = out + (size_t)(blockIdx.x * 256 + warp * 32) * 64;
#pragma unroll
    for (int i = 0; i < 2; i++) {
#pragma unroll
        for (int j = 0; j < 8; j++) {
            int col = j * 8 + t * 2;
            float2 v0 = make_float2(acc[i][j][0], acc[i][j][1]);
            float2 v1 = make_float2(acc[i][j][2], acc[i][j][3]);
            *(float2*)(ob + (i * 16 + g    ) * 64 + col) = v0;
            *(float2*)(ob + (i * 16 + g + 8) * 64 + col) = v1;
        }
    }
}

// ---------------- fused attention apply + 3 exp MLP stages ------------------
// 256 rows/block, double-buffered weight copies from pre-permuted global.
__global__ __launch_bounds__(256, 2) void attn_mlp_tc(
    const float* __restrict__ eb,
    const float* __restrict__ eg, const float* __restrict__ ebe)
{
    extern __shared__ float sm[];
    float*    Xs  = sm;
    uint32_t* Wb  = (uint32_t*)(sm + 256 * XS_STRIDE);       // 2 buffers
    float*    Pp  = (float*)(Wb + 2 * 64 * WS_STRIDE);       // 2 x 192
    float*    Ksm = Pp + 2 * 192;

    int tid = threadIdx.x, warp = tid >> 5, lane = tid & 31;
    int g = lane >> 2, t = lane & 3;
    int bh = blockIdx.x >> 4;
    int n0 = (blockIdx.x & 15) << 8;

    const float* qb = g_q + ((size_t)bh * 4096 + n0) * 64;
    for (int idx = tid; idx < 256 * 16; idx += 256) {
        int r = idx >> 4, c4 = (idx & 15) << 2;
        *(float4*)&Xs[r * XS_STRIDE + c4] = *(const float4*)(qb + r * 64 + c4);
    }
    copy_w_smem(Wb, g_kvt + bh * 4096, tid);                 // buf0 <- kv
    if (tid < 64) Ksm[tid] = g_ksum[bh * 64 + tid];
    __syncthreads();

    const float* Xw  = Xs + warp * 32 * XS_STRIDE;
    float*       Xwm = Xs + warp * 32 * XS_STRIDE;

    // preload stage s=2 into buf1 (overlaps with q@kv compute)
    copy_w_smem(Wb + 64 * WS_STRIDE, g_ewt + 2 * 4096, tid);
    if (tid < 64) {
        Pp[192 + tid]       = eb[2 * 64 + tid];
        Pp[192 + 64 + tid]  = eg[2 * 64 + tid];
        Pp[192 + 128 + tid] = ebe[2 * 64 + tid];
    }

    float acc[2][8][4];
#pragma unroll
    for (int i = 0; i < 2; i++)
#pragma unroll
        for (int j = 0; j < 8; j++)
#pragma unroll
            for (int q = 0; q < 4; q++) acc[i][j][q] = 0.0f;

    mma_block64(acc, Xw, Wb, g, t);

    float inv2[2][2];
#pragma unroll
    for (int i = 0; i < 2; i++) {
#pragma unroll
        for (int hlf = 0; hlf < 2; hlf++) {
            const float* xr = Xw + (i * 16 + g + hlf * 8) * XS_STRIDE;
            float dp = 0.0f;
#pragma unroll
            for (int e = 0; e < 16; e++) dp += xr[t + e * 4] * Ksm[t + e * 4];
            dp += __shfl_xor_sync(~0u, dp, 1);
            dp += __shfl_xor_sync(~0u, dp, 2);
            inv2[i][hlf] = 1.0f / (dp + 1e-6f);
        }
    }
#pragma unroll
    for (int i = 0; i < 2; i++) {
#pragma unroll
        for (int j = 0; j < 8; j++) {
            int col = j * 8 + t * 2;
            float2 v0 = make_float2(acc[i][j][0] * inv2[i][0], acc[i][j][1] * inv2[i][0]);
            float2 v1 = make_float2(acc[i][j][2] * inv2[i][1], acc[i][j][3] * inv2[i][1]);
            *(float2*)&Xwm[(i * 16 + g    ) * XS_STRIDE + col] = v0;
            *(float2*)&Xwm[(i * 16 + g + 8) * XS_STRIDE + col] = v1;
        }
    }
    __syncthreads();   // buf1 (s=2) ready; all reads of buf0 done

    int b = bh / Hh, h = bh - b * Hh;
    float* obase = g_attn + ((size_t)b * 4096 + n0 + warp * 32) * DIMC + h * 64;

#pragma unroll 1
    for (int s = 2; s >= 0; s--) {
        int buf = (s == 1) ? 0 : 1;
        if (s > 0) {
            copy_w_smem(Wb + (1 - buf) * 64 * WS_STRIDE, g_ewt + (s - 1) * 4096, tid);
            if (tid < 64) {
                float* Pd = Pp + (1 - buf) * 192;
                Pd[tid]       = eb[(s - 1) * 64 + tid];
                Pd[64 + tid]  = eg[(s - 1) * 64 + tid];
                Pd[128 + tid] = ebe[(s - 1) * 64 + tid];
            }
        }

#pragma unroll
        for (int i = 0; i < 2; i++)
#pragma unroll
            for (int j = 0; j < 8; j++)
#pragma unroll
                for (int q = 0; q < 4; q++) acc[i][j][q] = 0.0f;

        const float* Pd = Pp + buf * 192;
        mma_block64(acc, Xw, Wb + buf * 64 * WS_STRIDE, g, t);
        ln_gelu_regs(acc, Pd, Pd + 64, Pd + 128, t);

        if (s > 0) {
#pragma unroll
            for (int i = 0; i < 2; i++) {
#pragma unroll
                for (int j = 0; j < 8; j++) {
                    int col = j * 8 + t * 2;
                    *(float2*)&Xwm[(i * 16 + g    ) * XS_STRIDE + col] =
                        make_float2(acc[i][j][0], acc[i][j][1]);
                    *(float2*)&Xwm[(i * 16 + g + 8) * XS_STRIDE + col] =
                        make_float2(acc[i][j][2], acc[i][j][3]);
                }
            }
            __syncthreads();
        } else {
            // final stage: store tf32 bit-patterns for out_gemm
#pragma unroll
            for (int i = 0; i < 2; i++) {
#pragma unroll
                for (int j = 0; j < 8; j++) {
                    int col = j * 8 + t * 2;
                    *(float2*)(obase + (size_t)(i * 16 + g    ) * DIMC + col) =
                        make_float2(__uint_as_float(f2tf32(acc[i][j][0])),
                                    __uint_as_float(f2tf32(acc[i][j][1])));
                    *(float2*)(obase + (size_t)(i * 16 + g + 8) * DIMC + col) =
                        make_float2(__uint_as_float(f2tf32(acc[i][j][2])),
                                    __uint_as_float(f2tf32(acc[i][j][3])));
                }
            }
        }
    }
}

// ---------------- vc pooling: mean over 8 consecutive tokens ----------------
__global__ void vpool_kernel()
{
    int idx = blockIdx.x * 256 + threadIdx.x;
    if (idx >= BH * 512 * Dh) return;
    int d   = idx & 63;
    int rest = idx >> 6;
    int n   = rest & 511;
    int bh  = rest >> 9;
    const float* src = g_v + (bh * 4096 + n * 8) * 64 + d;
    float s = 0.0f;
#pragma unroll
    for (int j = 0; j < 8; j++) s += src[j * 64];
    g_vc[idx] = s * 0.125f;
}

// ---------------- kv = (kc/sqrt(512))^T vc + k_sum; stores permuted tf32 ----
__global__ __launch_bounds__(256) void kv_kernel()
{
    int bh = blockIdx.x;
    __shared__ float ks[64][65];
    __shared__ float vs[64][65];
    int tid = threadIdx.x;
    int td = tid & 15, te = tid >> 4;
    float acc[4][4];
#pragma unroll
    for (int i = 0; i < 4; i++)
#pragma unroll
        for (int j = 0; j < 4; j++) acc[i][j] = 0.0f;
    float colsum = 0.0f;
    const float scale = rsqrtf(512.0f);

    for (int nt = 0; nt < 512; nt += 64) {
        for (int i = tid; i < 4096; i += 256) {
            int rr = i >> 6, cc = i & 63;
            ks[rr][cc] = g_kcA[(bh * 512 + nt + rr) * 64 + cc] * scale;
            vs[rr][cc] = g_vc [(bh * 512 + nt + rr) * 64 + cc];
        }
        __syncthreads();
        if (tid < 64) {
            for (int rr = 0; rr < 64; rr++) colsum += ks[rr][tid];
        }
#pragma unroll 4
        for (int nn = 0; nn < 64; nn++) {
            float a[4], bb[4];
#pragma unroll
            for (int i = 0; i < 4; i++) a[i]  = ks[nn][td * 4 + i];
#pragma unroll
            for (int j = 0; j < 4; j++) bb[j] = vs[nn][te * 4 + j];
#pragma unroll
            for (int i = 0; i < 4; i++)
#pragma unroll
                for (int j = 0; j < 4; j++)
                    acc[i][j] = fmaf(a[i], bb[j], acc[i][j]);
        }
        __syncthreads();
    }
    // store permuted tf32 bits: row r (k-dim), col c -> r*64 + (c%8)*8 + c/8
#pragma unroll
    for (int i = 0; i < 4; i++) {
#pragma unroll
        for (int j = 0; j < 4; j++) {
            int r = td * 4 + i, c = te * 4 + j;
            g_kvt[bh * 4096 + r * 64 + ((c & 7) << 3) + (c >> 3)] = f2tf32(acc[i][j]);
        }
    }
    if (tid < 64) g_ksum[bh * 64 + tid] = colsum;
}

// ---------------- launch --------------------------------------------------
extern "C" void kernel_launch(void* const* d_in, const int* in_sizes, int n_in,
                              void* d_out, int out_size)
{
    const float* x   = (const float*)d_in[0];
    const float* Wq  = (const float*)d_in[1];
    const float* Wk  = (const float*)d_in[2];
    const float* Wv  = (const float*)d_in[3];
    const float* pW  = (const float*)d_in[4];
    const float* pb  = (const float*)d_in[5];
    const float* pg  = (const float*)d_in[6];
    const float* pbe = (const float*)d_in[7];
    const float* eW  = (const float*)d_in[8];
    const float* eb  = (const float*)d_in[9];
    const float* eg  = (const float*)d_in[10];
    const float* ebe = (const float*)d_in[11];
    const float* Wo  = (const float*)d_in[12];
    const float* bo  = (const float*)d_in[13];
    float* out = (float*)d_out;

    cudaFuncSetAttribute(qkv_gemm,
        cudaFuncAttributeMaxDynamicSharedMemorySize, GEMM_SMEM_BYTES);
    cudaFuncSetAttribute(out_gemm,
        cudaFuncAttributeMaxDynamicSharedMemorySize, GEMM_SMEM_BYTES);
    cudaFuncSetAttribute(pool_mlp_tc,
        cudaFuncAttributeMaxDynamicSharedMemorySize, POOL_SMEM_BYTES);
    cudaFuncSetAttribute(attn_mlp_tc,
        cudaFuncAttributeMaxDynamicSharedMemorySize, ATTN_SMEM_BYTES);

    prep_x<<<(MR * DIMC / 4 + 255) / 256, 256>>>((const float4*)x);
    prep_w<<<(4 * DIMC * DIMC / 4 + 255) / 256, 256>>>(
        (const float4*)Wq, (const float4*)Wk, (const float4*)Wv, (const float4*)Wo);
    prep_small<<<(2 * 3 * 4096 + 255) / 256, 256>>>(eW, pW);

    qkv_gemm<<<dim3(18, MR / 128), 256, GEMM_SMEM_BYTES>>>();
    vpool_kernel<<<(BH * 512 * Dh + 255) / 256, 256>>>();
    pool_mlp_tc<<<BH * 2048 / 256, 256, POOL_SMEM_BYTES>>>(0, pb, pg, pbe);
    pool_mlp_tc<<<BH * 1024 / 256, 256, POOL_SMEM_BYTES>>>(1, pb, pg, pbe);
    pool_mlp_tc<<<BH * 512 / 256, 256, POOL_SMEM_BYTES>>>(2, pb, pg, pbe);
    kv_kernel<<<BH, 256>>>();
    attn_mlp_tc<<<BH * 16, 256, ATTN_SMEM_BYTES>>>(eb, eg, ebe);
    out_gemm<<<dim3(6, MR / 128), 256, GEMM_SMEM_BYTES>>>(bo, out);
}

// round 15
// speedup vs baseline: 1.0740x; 1.0085x over previous
#include <cuda_runtime.h>
#include <math.h>
#include <stdint.h>

#define Bz   8
#define Nseq 4096
#define DIMC 768
#define Hh   12
#define Dh   64
#define BH   (Bz*Hh)        // 96
#define MR   (Bz*Nseq)      // 32768

// ---------------- scratch (device globals; no allocations allowed) ----------
__device__ float g_q[BH*Nseq*Dh];
__device__ float g_k[BH*Nseq*Dh];
__device__ float g_v[BH*Nseq*Dh];
__device__ float g_kcA[BH*2048*Dh];
__device__ float g_kcB[BH*1024*Dh];
__device__ float g_vc[BH*512*Dh];
__device__ float g_ksum[BH*Dh];
__device__ float g_attn[MR*DIMC];          // holds tf32 bit-patterns (as float)
__device__ uint32_t g_xt[MR*DIMC];         // X pre-converted to tf32 bits
__device__ uint32_t g_wqt[DIMC*DIMC];
__device__ uint32_t g_wkt[DIMC*DIMC];
__device__ uint32_t g_wvt[DIMC*DIMC];
__device__ uint32_t g_wot[DIMC*DIMC];
__device__ uint32_t g_kvt[BH*Dh*Dh];       // kv, permuted tf32 layout
__device__ uint32_t g_ewt[3*Dh*Dh];        // exp weights, permuted tf32
__device__ uint32_t g_pwt[3*Dh*Dh];        // pool weights, permuted tf32

__device__ __forceinline__ float gelu_f(float t) {
    return 0.5f * t * (1.0f + erff(t * 0.70710678118654752f));
}
__device__ __forceinline__ float fmap_f(float t) {   // elu(t)+1
    return t > 0.0f ? t + 1.0f : expf(t);
}
__device__ __forceinline__ uint32_t f2tf32(float f) {
    uint32_t r;
    asm("cvt.rna.tf32.f32 %0, %1;" : "=r"(r) : "f"(f));
    return r;
}
__device__ __forceinline__ void mma_tf32(float c[4],
    uint32_t a0, uint32_t a1, uint32_t a2, uint32_t a3,
    uint32_t b0, uint32_t b1)
{
    asm volatile(
        "mma.sync.aligned.m16n8k8.row.col.f32.tf32.tf32.f32 "
        "{%0,%1,%2,%3}, {%4,%5,%6,%7}, {%8,%9}, {%0,%1,%2,%3};"
        : "+f"(c[0]), "+f"(c[1]), "+f"(c[2]), "+f"(c[3])
        : "r"(a0), "r"(a1), "r"(a2), "r"(a3), "r"(b0), "r"(b1));
}
__device__ __forceinline__ void cp_async16(uint32_t dst, const void* src) {
    asm volatile("cp.async.cg.shared.global [%0], [%1], 16;" :: "r"(dst), "l"(src));
}

// ---------------- prepasses: fp32 -> tf32 bit patterns ----------------------
__global__ void prep_x(const float4* __restrict__ src)
{
    int i = blockIdx.x * 256 + threadIdx.x;
    if (i < MR * DIMC / 4) {
        float4 v = src[i];
        uint4 o;
        o.x = f2tf32(v.x); o.y = f2tf32(v.y);
        o.z = f2tf32(v.z); o.w = f2tf32(v.w);
        ((uint4*)g_xt)[i] = o;
    }
}
__global__ void prep_w(const float4* __restrict__ wq, const float4* __restrict__ wk,
                       const float4* __restrict__ wv, const float4* __restrict__ wo)
{
    const int n4 = DIMC * DIMC / 4;
    int i = blockIdx.x * 256 + threadIdx.x;
    if (i >= 4 * n4) return;
    int seg = i / n4, r = i - seg * n4;
    const float4* s = (seg == 0) ? wq : (seg == 1) ? wk : (seg == 2) ? wv : wo;
    uint4* d = (seg == 0) ? (uint4*)g_wqt : (seg == 1) ? (uint4*)g_wkt
             : (seg == 2) ? (uint4*)g_wvt : (uint4*)g_wot;
    float4 v = s[r];
    uint4 o;
    o.x = f2tf32(v.x); o.y = f2tf32(v.y);
    o.z = f2tf32(v.z); o.w = f2tf32(v.w);
    d[r] = o;
}
// small weights (eW, pW) -> permuted tf32 dense arrays
__global__ void prep_small(const float* __restrict__ eW, const float* __restrict__ pW)
{
    int i = blockIdx.x * 256 + threadIdx.x;
    if (i >= 2 * 3 * 4096) return;
    int which = i / (3 * 4096);
    int rem   = i - which * (3 * 4096);
    const float* src = which ? pW : eW;
    uint32_t*    dst = which ? g_pwt : g_ewt;
    int rc = rem & 4095;
    int c = rc & 63;
    dst[(rem & ~4095) + (rc & ~63) + ((c & 7) << 3) + (c >> 3)] = f2tf32(src[rem]);
}

// =======================================================================
// Big GEMMs: tf32, 3-stage cp.async pipeline, ONE barrier per k-tile.
// =======================================================================
#define AS_STRIDE 36
#define BS_STRIDE 136
#define AS_TILE   (128 * AS_STRIDE)
#define BS_TILE   (32 * BS_STRIDE)
#define NT        (DIMC / 32)
#define NSTAGE    3
#define GEMM_SMEM_BYTES (NSTAGE * (AS_TILE + BS_TILE) * 4)

#define GEMM_PROLOG \
    extern __shared__ uint32_t smemg[]; \
    uint32_t* Asf = smemg; \
    uint32_t* Bsf = smemg + NSTAGE * AS_TILE; \
    uint32_t As_base = (uint32_t)__cvta_generic_to_shared(Asf); \
    uint32_t Bs_base = (uint32_t)__cvta_generic_to_shared(Bsf); \
    int tid = threadIdx.x; \
    int warp = tid >> 5, lane = tid & 31; \
    int g = lane >> 2, t = lane & 3; \
    int wm = warp >> 1, wn = warp & 1; \
    int a_row = tid >> 1, a_col = (tid & 1) << 4; \
    int b_row = tid >> 3, b_col = (tid & 7) << 4; \
    float acc[2][8][4]; \
    _Pragma("unroll") \
    for (int i = 0; i < 2; i++) \
        _Pragma("unroll") \
        for (int j = 0; j < 8; j++) \
            _Pragma("unroll") \
            for (int q = 0; q < 4; q++) acc[i][j][q] = 0.0f;

#define GEMM_CPLOAD(APTR_BASE, K0, BUF) { \
    const uint32_t* ap_ = (APTR_BASE) + (K0) + a_col; \
    const uint32_t* bp_ = W + (size_t)((K0) + b_row) * DIMC + n0 + b_col; \
    uint32_t asd = As_base + (uint32_t)(((BUF) * AS_TILE + a_row * AS_STRIDE + a_col) * 4); \
    uint32_t bsd = Bs_base + (uint32_t)(((BUF) * BS_TILE + b_row * BS_STRIDE + b_col) * 4); \
    _Pragma("unroll") \
    for (int u = 0; u < 4; u++) { \
        cp_async16(asd + u * 16, ap_ + u * 4); \
        cp_async16(bsd + u * 16, bp_ + u * 4); \
    } }

#define GEMM_COMPUTE(BUF) { \
    const uint32_t* Asc = Asf + (BUF) * AS_TILE; \
    const uint32_t* Bsc = Bsf + (BUF) * BS_TILE; \
    _Pragma("unroll") \
    for (int kk = 0; kk < 4; kk++) { \
        int ks = kk * 8; \
        uint32_t af[2][4]; \
        _Pragma("unroll") \
        for (int i = 0; i < 2; i++) { \
            int rb = wm * 32 + i * 16; \
            af[i][0] = Asc[(rb + g    ) * AS_STRIDE + ks + t    ]; \
            af[i][1] = Asc[(rb + g + 8) * AS_STRIDE + ks + t    ]; \
            af[i][2] = Asc[(rb + g    ) * AS_STRIDE + ks + t + 4]; \
            af[i][3] = Asc[(rb + g + 8) * AS_STRIDE + ks + t + 4]; \
        } \
        uint32_t bf[8][2]; \
        _Pragma("unroll") \
        for (int j = 0; j < 8; j++) { \
            int cb = wn * 64 + j * 8 + g; \
            bf[j][0] = Bsc[(ks + t    ) * BS_STRIDE + cb]; \
            bf[j][1] = Bsc[(ks + t + 4) * BS_STRIDE + cb]; \
        } \
        _Pragma("unroll") \
        for (int i = 0; i < 2; i++) \
            _Pragma("unroll") \
            for (int j = 0; j < 8; j++) \
                mma_tf32(acc[i][j], af[i][0], af[i][1], af[i][2], af[i][3], \
                         bf[j][0], bf[j][1]); \
    } }

// 3-stage: prefetch 0,1; per iter: wait(<=1 outstanding) -> barrier ->
// prefetch kt+2 (overwrites stage (kt-1)%3, safe past barrier) -> compute kt.
#define GEMM_MAINLOOP(APTR_BASE) \
    GEMM_CPLOAD(APTR_BASE, 0, 0) \
    asm volatile("cp.async.commit_group;"); \
    GEMM_CPLOAD(APTR_BASE, 32, 1) \
    asm volatile("cp.async.commit_group;"); \
    _Pragma("unroll 1") \
    for (int kt = 0; kt < NT; kt++) { \
        asm volatile("cp.async.wait_group 1;"); \
        __syncthreads(); \
        if (kt + 2 < NT) { \
            GEMM_CPLOAD(APTR_BASE, (kt + 2) * 32, (kt + 2) % 3) \
            asm volatile("cp.async.commit_group;"); \
        } else { \
            asm volatile("cp.async.commit_group;"); \
        } \
        GEMM_COMPUTE(kt % 3) \
    }

__global__ __launch_bounds__(256, 2) void qkv_gemm()
{
    GEMM_PROLOG
    int nb   = blockIdx.x;
    int wsel = nb / 6;
    const uint32_t* W = (wsel == 0) ? g_wqt : (wsel == 1 ? g_wkt : g_wvt);
    float*          O = (wsel == 0) ? g_q : (wsel == 1 ? g_k : g_v);
    int n0 = (nb % 6) * 128;
    int m0 = blockIdx.y * 128;
    const uint32_t* Abase = g_xt + (size_t)(m0 + a_row) * DIMC;

    GEMM_MAINLOOP(Abase)

#pragma unroll
    for (int i = 0; i < 2; i++) {
#pragma unroll
        for (int j = 0; j < 8; j++) {
            int r0 = m0 + wm * 32 + i * 16 + g;
            int c  = n0 + wn * 64 + j * 8 + t * 2;
            int h = c >> 6, d = c & 63;
#pragma unroll
            for (int half = 0; half < 2; half++) {
                int m = half ? r0 + 8 : r0;
                int b = m >> 12, n = m & 4095;
                float v0 = acc[i][j][half * 2 + 0];
                float v1 = acc[i][j][half * 2 + 1];
                if (wsel < 2) { v0 = fmap_f(v0); v1 = fmap_f(v1); }
                float* dst = O + (((size_t)(b * Hh + h) * Nseq + n) * Dh + d);
                dst[0] = v0; dst[1] = v1;
            }
        }
    }
}

__global__ __launch_bounds__(256, 2) void out_gemm(
    const float* __restrict__ bias, float* __restrict__ out)
{
    GEMM_PROLOG
    int n0 = blockIdx.x * 128;
    int m0 = blockIdx.y * 128;
    const uint32_t* W = g_wot;
    const uint32_t* Abase = (const uint32_t*)g_attn + (size_t)(m0 + a_row) * DIMC;

    GEMM_MAINLOOP(Abase)

#pragma unroll
    for (int i = 0; i < 2; i++) {
#pragma unroll
        for (int j = 0; j < 8; j++) {
            int r0 = m0 + wm * 32 + i * 16 + g;
            int c  = n0 + wn * 64 + j * 8 + t * 2;
            float b0 = bias[c], b1 = bias[c + 1];
            out[(size_t)r0 * DIMC + c]           = acc[i][j][0] + b0;
            out[(size_t)r0 * DIMC + c + 1]       = acc[i][j][1] + b1;
            out[(size_t)(r0 + 8) * DIMC + c]     = acc[i][j][2] + b0;
            out[(size_t)(r0 + 8) * DIMC + c + 1] = acc[i][j][3] + b1;
        }
    }
}

// =======================================================================
// Tensor-core 64-wide MLP machinery — single tf32, permuted W layout.
// Weights are pre-permuted+converted in GLOBAL; loaders are uint4 copies.
// =======================================================================
#define XS_STRIDE 68
#define WS_STRIDE 72
#define POOL_SMEM_FLOATS (256 * XS_STRIDE + 64 * WS_STRIDE + 192)
#define POOL_SMEM_BYTES  (POOL_SMEM_FLOATS * 4)
#define ATTN_SMEM_FLOATS (256 * XS_STRIDE + 2 * 64 * WS_STRIDE + 2 * 192 + 64)
#define ATTN_SMEM_BYTES  (ATTN_SMEM_FLOATS * 4)

// vectorized copy of a pre-permuted 64x64 weight tile into smem (stride rows)
__device__ __forceinline__ void copy_w_smem(
    uint32_t* Wd, const uint32_t* __restrict__ src, int tid)
{
    for (int idx = tid * 4; idx < 4096; idx += 1024) {
        uint4 v = *(const uint4*)(src + idx);
        *(uint4*)(Wd + (idx >> 6) * WS_STRIDE + (idx & 63)) = v;
    }
}

__device__ __forceinline__ void mma_block64(
    float acc[2][8][4], const float* Xw, const uint32_t* Ws, int g, int t)
{
#pragma unroll
    for (int ks8 = 0; ks8 < 8; ks8++) {
        int ks = ks8 * 8;
        uint32_t af[2][4];
#pragma unroll
        for (int i = 0; i < 2; i++) {
            const float* xr = Xw + (i * 16 + g) * XS_STRIDE + ks;
            af[i][0] = f2tf32(xr[t]);
            af[i][1] = f2tf32(xr[8 * XS_STRIDE + t]);
            af[i][2] = f2tf32(xr[t + 4]);
            af[i][3] = f2tf32(xr[8 * XS_STRIDE + t + 4]);
        }
        const uint32_t* w0 = Ws + (ks + t    ) * WS_STRIDE + g * 8;
        const uint32_t* w1 = Ws + (ks + t + 4) * WS_STRIDE + g * 8;
        uint4 b0a = *(const uint4*)w0;
        uint4 b0b = *(const uint4*)(w0 + 4);
        uint4 b1a = *(const uint4*)w1;
        uint4 b1b = *(const uint4*)(w1 + 4);
        uint32_t b0[8] = {b0a.x, b0a.y, b0a.z, b0a.w, b0b.x, b0b.y, b0b.z, b0b.w};
        uint32_t b1[8] = {b1a.x, b1a.y, b1a.z, b1a.w, b1b.x, b1b.y, b1b.z, b1b.w};
#pragma unroll
        for (int j = 0; j < 8; j++)
#pragma unroll
            for (int i = 0; i < 2; i++)
                mma_tf32(acc[i][j], af[i][0], af[i][1], af[i][2], af[i][3],
                         b0[j], b1[j]);
    }
}

__device__ __forceinline__ void ln_gelu_regs(
    float acc[2][8][4], const float* Pb, const float* Pg, const float* Pe, int t)
{
#pragma unroll
    for (int i = 0; i < 2; i++) {
        float s1A = 0, s2A = 0, s1B = 0, s2B = 0;
#pragma unroll
        for (int j = 0; j < 8; j++) {
#pragma unroll
            for (int q = 0; q < 4; q++) {
                int col = j * 8 + t * 2 + (q & 1);
                float v = acc[i][j][q] + Pb[col];
                acc[i][j][q] = v;
                if (q < 2) { s1A += v; s2A += v * v; }
                else       { s1B += v; s2B += v * v; }
            }
        }
        s1A += __shfl_xor_sync(~0u, s1A, 1); s2A += __shfl_xor_sync(~0u, s2A, 1);
        s1B += __shfl_xor_sync(~0u, s1B, 1); s2B += __shfl_xor_sync(~0u, s2B, 1);
        s1A += __shfl_xor_sync(~0u, s1A, 2); s2A += __shfl_xor_sync(~0u, s2A, 2);
        s1B += __shfl_xor_sync(~0u, s1B, 2); s2B += __shfl_xor_sync(~0u, s2B, 2);
        float muA = s1A * (1.0f / 64.0f);
        float muB = s1B * (1.0f / 64.0f);
        float rA = rsqrtf(s2A * (1.0f / 64.0f) - muA * muA + 1e-5f);
        float rB = rsqrtf(s2B * (1.0f / 64.0f) - muB * muB + 1e-5f);
#pragma unroll
        for (int j = 0; j < 8; j++) {
#pragma unroll
            for (int q = 0; q < 4; q++) {
                int col = j * 8 + t * 2 + (q & 1);
                float mu = (q < 2) ? muA : muB;
                float rv = (q < 2) ? rA : rB;
                acc[i][j][q] = gelu_f((acc[i][j][q] - mu) * rv * Pg[col] + Pe[col]);
            }
        }
    }
}

// ---------------- pool stage (tensor core): pair-mean + MLP(LN+gelu) --------
__global__ __launch_bounds__(256, 2) void pool_mlp_tc(
    int stage,
    const float* __restrict__ pb,
    const float* __restrict__ pg, const float* __restrict__ pbe)
{
    extern __shared__ float sm[];
    float*    Xs = sm;
    uint32_t* Ws = (uint32_t*)(sm + 256 * XS_STRIDE);
    float*    Pb = (float*)(Ws + 64 * WS_STRIDE);
    float*    Pg = Pb + 64;
    float*    Pe = Pg + 64;

    const float* in; float* out; int s_in, s_out;
    if (stage == 0)      { in = g_k;   out = g_kcA; s_in = 4096; s_out = 2048; }
    else if (stage == 1) { in = g_kcA; out = g_kcB; s_in = 2048; s_out = 1024; }
    else                 { in = g_kcB; out = g_kcA; s_in = 1024; s_out = 512;  }

    int tid = threadIdx.x, warp = tid >> 5, lane = tid & 31;
    int g = lane >> 2, t = lane & 3;

    for (int idx = tid; idx < 256 * 16; idx += 256) {
        int r = idx >> 4, c4 = (idx & 15) << 2;
        int rg = blockIdx.x * 256 + r;
        int bh = rg / s_out, n = rg - bh * s_out;
        const float* src = in + ((size_t)bh * s_in + 2 * n) * 64 + c4;
        float4 a = *(const float4*)src;
        float4 b = *(const float4*)(src + 64);
        float4 v;
        v.x = 0.5f * (a.x + b.x); v.y = 0.5f * (a.y + b.y);
        v.z = 0.5f * (a.z + b.z); v.w = 0.5f * (a.w + b.w);
        *(float4*)&Xs[r * XS_STRIDE + c4] = v;
    }
    copy_w_smem(Ws, g_pwt + stage * 4096, tid);
    if (tid < 64) {
        Pb[tid] = pb[stage * 64 + tid];
        Pg[tid] = pg[stage * 64 + tid];
        Pe[tid] = pbe[stage * 64 + tid];
    }
    __syncthreads();

    float acc[2][8][4];
#pragma unroll
    for (int i = 0; i < 2; i++)
#pragma unroll
        for (int j = 0; j < 8; j++)
#pragma unroll
            for (int q = 0; q < 4; q++) acc[i][j][q] = 0.0f;

    mma_block64(acc, Xs + warp * 32 * XS_STRIDE, Ws, g, t);
    ln_gelu_regs(acc, Pb, Pg, Pe, t);

    float* ob = out + (size_t)(blockIdx.x * 256 + warp * 32) * 64;
#pragma unroll
    for (int i = 0; i < 2; i++) {
#pragma unroll
        for (int j = 0; j < 8; j++) {
            int col = j * 8 + t * 2;
            float2 v0 = make_float2(acc[i][j][0], acc[i][j][1]);
            float2 v1 = make_float2(acc[i][j][2], acc[i][j][3]);
            *(float2*)(ob + (i * 16 + g    ) * 64 + col) = v0;
            *(float2*)(ob + (i * 16 + g + 8) * 64 + col) = v1;
        }
    }
}

// ---------------- fused attention apply + 3 exp MLP stages ------------------
// 256 rows/block, double-buffered weight copies from pre-permuted global.
__global__ __launch_bounds__(256, 2) void attn_mlp_tc(
    const float* __restrict__ eb,
    const float* __restrict__ eg, const float* __restrict__ ebe)
{
    extern __shared__ float sm[];
    float*    Xs  = sm;
    uint32_t* Wb  = (uint32_t*)(sm + 256 * XS_STRIDE);       // 2 buffers
    float*    Pp  = (float*)(Wb + 2 * 64 * WS_STRIDE);       // 2 x 192
    float*    Ksm = Pp + 2 * 192;

    int tid = threadIdx.x, warp = tid >> 5, lane = tid & 31;
    int g = lane >> 2, t = lane & 3;
    int bh = blockIdx.x >> 4;
    int n0 = (blockIdx.x & 15) << 8;

    const float* qb = g_q + ((size_t)bh * 4096 + n0) * 64;
    for (int idx = tid; idx < 256 * 16; idx += 256) {
        int r = idx >> 4, c4 = (idx & 15) << 2;
        *(float4*)&Xs[r * XS_STRIDE + c4] = *(const float4*)(qb + r * 64 + c4);
    }
    copy_w_smem(Wb, g_kvt + bh * 4096, tid);                 // buf0 <- kv
    if (tid < 64) Ksm[tid] = g_ksum[bh * 64 + tid];
    __syncthreads();

    const float* Xw  = Xs + warp * 32 * XS_STRIDE;
    float*       Xwm = Xs + warp * 32 * XS_STRIDE;

    // preload stage s=2 into buf1 (overlaps with q@kv compute)
    copy_w_smem(Wb + 64 * WS_STRIDE, g_ewt + 2 * 4096, tid);
    if (tid < 64) {
        Pp[192 + tid]       = eb[2 * 64 + tid];
        Pp[192 + 64 + tid]  = eg[2 * 64 + tid];
        Pp[192 + 128 + tid] = ebe[2 * 64 + tid];
    }

    float acc[2][8][4];
#pragma unroll
    for (int i = 0; i < 2; i++)
#pragma unroll
        for (int j = 0; j < 8; j++)
#pragma unroll
            for (int q = 0; q < 4; q++) acc[i][j][q] = 0.0f;

    mma_block64(acc, Xw, Wb, g, t);

    float inv2[2][2];
#pragma unroll
    for (int i = 0; i < 2; i++) {
#pragma unroll
        for (int hlf = 0; hlf < 2; hlf++) {
            const float* xr = Xw + (i * 16 + g + hlf * 8) * XS_STRIDE;
            float dp = 0.0f;
#pragma unroll
            for (int e = 0; e < 16; e++) dp += xr[t + e * 4] * Ksm[t + e * 4];
            dp += __shfl_xor_sync(~0u, dp, 1);
            dp += __shfl_xor_sync(~0u, dp, 2);
            inv2[i][hlf] = 1.0f / (dp + 1e-6f);
        }
    }
#pragma unroll
    for (int i = 0; i < 2; i++) {
#pragma unroll
        for (int j = 0; j < 8; j++) {
            int col = j * 8 + t * 2;
            float2 v0 = make_float2(acc[i][j][0] * inv2[i][0], acc[i][j][1] * inv2[i][0]);
            float2 v1 = make_float2(acc[i][j][2] * inv2[i][1], acc[i][j][3] * inv2[i][1]);
            *(float2*)&Xwm[(i * 16 + g    ) * XS_STRIDE + col] = v0;
            *(float2*)&Xwm[(i * 16 + g + 8) * XS_STRIDE + col] = v1;
        }
    }
    __syncthreads();   // buf1 (s=2) ready; all reads of buf0 done

    int b = bh / Hh, h = bh - b * Hh;
    float* obase = g_attn + ((size_t)b * 4096 + n0 + warp * 32) * DIMC + h * 64;

#pragma unroll 1
    for (int s = 2; s >= 0; s--) {
        int buf = (s == 1) ? 0 : 1;
        if (s > 0) {
            copy_w_smem(Wb + (1 - buf) * 64 * WS_STRIDE, g_ewt + (s - 1) * 4096, tid);
            if (tid < 64) {
                float* Pd = Pp + (1 - buf) * 192;
                Pd[tid]       = eb[(s - 1) * 64 + tid];
                Pd[64 + tid]  = eg[(s - 1) * 64 + tid];
                Pd[128 + tid] = ebe[(s - 1) * 64 + tid];
            }
        }

#pragma unroll
        for (int i = 0; i < 2; i++)
#pragma unroll
            for (int j = 0; j < 8; j++)
#pragma unroll
                for (int q = 0; q < 4; q++) acc[i][j][q] = 0.0f;

        const float* Pd = Pp + buf * 192;
        mma_block64(acc, Xw, Wb + buf * 64 * WS_STRIDE, g, t);
        ln_gelu_regs(acc, Pd, Pd + 64, Pd + 128, t);

        if (s > 0) {
#pragma unroll
            for (int i = 0; i < 2; i++) {
#pragma unroll
                for (int j = 0; j < 8; j++) {
                    int col = j * 8 + t * 2;
                    *(float2*)&Xwm[(i * 16 + g    ) * XS_STRIDE + col] =
                        make_float2(acc[i][j][0], acc[i][j][1]);
                    *(float2*)&Xwm[(i * 16 + g + 8) * XS_STRIDE + col] =
                        make_float2(acc[i][j][2], acc[i][j][3]);
                }
            }
            __syncthreads();
        } else {
            // final stage: store tf32 bit-patterns for out_gemm
#pragma unroll
            for (int i = 0; i < 2; i++) {
#pragma unroll
                for (int j = 0; j < 8; j++) {
                    int col = j * 8 + t * 2;
                    *(float2*)(obase + (size_t)(i * 16 + g    ) * DIMC + col) =
                        make_float2(__uint_as_float(f2tf32(acc[i][j][0])),
                                    __uint_as_float(f2tf32(acc[i][j][1])));
                    *(float2*)(obase + (size_t)(i * 16 + g + 8) * DIMC + col) =
                        make_float2(__uint_as_float(f2tf32(acc[i][j][2])),
                                    __uint_as_float(f2tf32(acc[i][j][3])));
                }
            }
        }
    }
}

// ---------------- vc pooling: mean over 8 consecutive tokens ----------------
__global__ void vpool_kernel()
{
    int idx = blockIdx.x * 256 + threadIdx.x;
    if (idx >= BH * 512 * Dh) return;
    int d   = idx & 63;
    int rest = idx >> 6;
    int n   = rest & 511;
    int bh  = rest >> 9;
    const float* src = g_v + (bh * 4096 + n * 8) * 64 + d;
    float s = 0.0f;
#pragma unroll
    for (int j = 0; j < 8; j++) s += src[j * 64];
    g_vc[idx] = s * 0.125f;
}

// ---------------- kv = (kc/sqrt(512))^T vc + k_sum; stores permuted tf32 ----
__global__ __launch_bounds__(256) void kv_kernel()
{
    int bh = blockIdx.x;
    __shared__ float ks[64][65];
    __shared__ float vs[64][65];
    int tid = threadIdx.x;
    int td = tid & 15, te = tid >> 4;
    float acc[4][4];
#pragma unroll
    for (int i = 0; i < 4; i++)
#pragma unroll
        for (int j = 0; j < 4; j++) acc[i][j] = 0.0f;
    float colsum = 0.0f;
    const float scale = rsqrtf(512.0f);

    for (int nt = 0; nt < 512; nt += 64) {
        for (int i = tid; i < 4096; i += 256) {
            int rr = i >> 6, cc = i & 63;
            ks[rr][cc] = g_kcA[(bh * 512 + nt + rr) * 64 + cc] * scale;
            vs[rr][cc] = g_vc [(bh * 512 + nt + rr) * 64 + cc];
        }
        __syncthreads();
        if (tid < 64) {
            for (int rr = 0; rr < 64; rr++) colsum += ks[rr][tid];
        }
#pragma unroll 4
        for (int nn = 0; nn < 64; nn++) {
            float a[4], bb[4];
#pragma unroll
            for (int i = 0; i < 4; i++) a[i]  = ks[nn][td * 4 + i];
#pragma unroll
            for (int j = 0; j < 4; j++) bb[j] = vs[nn][te * 4 + j];
#pragma unroll
            for (int i = 0; i < 4; i++)
#pragma unroll
                for (int j = 0; j < 4; j++)
                    acc[i][j] = fmaf(a[i], bb[j], acc[i][j]);
        }
        __syncthreads();
    }
    // store permuted tf32 bits: row r (k-dim), col c -> r*64 + (c%8)*8 + c/8
#pragma unroll
    for (int i = 0; i < 4; i++) {
#pragma unroll
        for (int j = 0; j < 4; j++) {
            int r = td * 4 + i, c = te * 4 + j;
            g_kvt[bh * 4096 + r * 64 + ((c & 7) << 3) + (c >> 3)] = f2tf32(acc[i][j]);
        }
    }
    if (tid < 64) g_ksum[bh * 64 + tid] = colsum;
}

// ---------------- launch --------------------------------------------------
extern "C" void kernel_launch(void* const* d_in, const int* in_sizes, int n_in,
                              void* d_out, int out_size)
{
    const float* x   = (const float*)d_in[0];
    const float* Wq  = (const float*)d_in[1];
    const float* Wk  = (const float*)d_in[2];
    const float* Wv  = (const float*)d_in[3];
    const float* pW  = (const float*)d_in[4];
    const float* pb  = (const float*)d_in[5];
    const float* pg  = (const float*)d_in[6];
    const float* pbe = (const float*)d_in[7];
    const float* eW  = (const float*)d_in[8];
    const float* eb  = (const float*)d_in[9];
    const float* eg  = (const float*)d_in[10];
    const float* ebe = (const float*)d_in[11];
    const float* Wo  = (const float*)d_in[12];
    const float* bo  = (const float*)d_in[13];
    float* out = (float*)d_out;

    cudaFuncSetAttribute(qkv_gemm,
        cudaFuncAttributeMaxDynamicSharedMemorySize, GEMM_SMEM_BYTES);
    cudaFuncSetAttribute(out_gemm,
        cudaFuncAttributeMaxDynamicSharedMemorySize, GEMM_SMEM_BYTES);
    cudaFuncSetAttribute(pool_mlp_tc,
        cudaFuncAttributeMaxDynamicSharedMemorySize, POOL_SMEM_BYTES);
    cudaFuncSetAttribute(attn_mlp_tc,
        cudaFuncAttributeMaxDynamicSharedMemorySize, ATTN_SMEM_BYTES);

    prep_x<<<(MR * DIMC / 4 + 255) / 256, 256>>>((const float4*)x);
    prep_w<<<(4 * DIMC * DIMC / 4 + 255) / 256, 256>>>(
        (const float4*)Wq, (const float4*)Wk, (const float4*)Wv, (const float4*)Wo);
    prep_small<<<(2 * 3 * 4096 + 255) / 256, 256>>>(eW, pW);

    qkv_gemm<<<dim3(18, MR / 128), 256, GEMM_SMEM_BYTES>>>();
    vpool_kernel<<<(BH * 512 * Dh + 255) / 256, 256>>>();
    pool_mlp_tc<<<BH * 2048 / 256, 256, POOL_SMEM_BYTES>>>(0, pb, pg, pbe);
    pool_mlp_tc<<<BH * 1024 / 256, 256, POOL_SMEM_BYTES>>>(1, pb, pg, pbe);
    pool_mlp_tc<<<BH * 512 / 256, 256, POOL_SMEM_BYTES>>>(2, pb, pg, pbe);
    kv_kernel<<<BH, 256>>>();
    attn_mlp_tc<<<BH * 16, 256, ATTN_SMEM_BYTES>>>(eb, eg, ebe);
    out_gemm<<<dim3(6, MR / 128), 256, GEMM_SMEM_BYTES>>>(bo, out);
}

// round 16
// speedup vs baseline: 1.0751x; 1.0010x over previous
#include <cuda_runtime.h>
#include <math.h>
#include <stdint.h>

#define Bz   8
#define Nseq 4096
#define DIMC 768
#define Hh   12
#define Dh   64
#define BH   (Bz*Hh)        // 96
#define MR   (Bz*Nseq)      // 32768

// ---------------- scratch (device globals; no allocations allowed) ----------
__device__ float g_q[BH*Nseq*Dh];
__device__ float g_k[BH*Nseq*Dh];
__device__ float g_v[BH*Nseq*Dh];
__device__ float g_kcA[BH*2048*Dh];
__device__ float g_kcB[BH*1024*Dh];
__device__ float g_vc[BH*512*Dh];
__device__ float g_ksum[BH*Dh];
__device__ float g_attn[MR*DIMC];          // holds tf32 bit-patterns (as float)
__device__ uint32_t g_xt[MR*DIMC];         // X pre-converted to tf32 bits
__device__ uint32_t g_wqt[DIMC*DIMC];
__device__ uint32_t g_wkt[DIMC*DIMC];
__device__ uint32_t g_wvt[DIMC*DIMC];
__device__ uint32_t g_wot[DIMC*DIMC];
__device__ uint32_t g_kvt[BH*Dh*Dh];       // kv, permuted tf32 layout
__device__ uint32_t g_ewt[3*Dh*Dh];        // exp weights, permuted tf32
__device__ uint32_t g_pwt[3*Dh*Dh];        // pool weights, permuted tf32

__device__ __forceinline__ float gelu_f(float t) {
    return 0.5f * t * (1.0f + erff(t * 0.70710678118654752f));
}
__device__ __forceinline__ float fmap_f(float t) {   // elu(t)+1
    return t > 0.0f ? t + 1.0f : expf(t);
}
__device__ __forceinline__ uint32_t f2tf32(float f) {
    uint32_t r;
    asm("cvt.rna.tf32.f32 %0, %1;" : "=r"(r) : "f"(f));
    return r;
}
__device__ __forceinline__ void mma_tf32(float c[4],
    uint32_t a0, uint32_t a1, uint32_t a2, uint32_t a3,
    uint32_t b0, uint32_t b1)
{
    asm volatile(
        "mma.sync.aligned.m16n8k8.row.col.f32.tf32.tf32.f32 "
        "{%0,%1,%2,%3}, {%4,%5,%6,%7}, {%8,%9}, {%0,%1,%2,%3};"
        : "+f"(c[0]), "+f"(c[1]), "+f"(c[2]), "+f"(c[3])
        : "r"(a0), "r"(a1), "r"(a2), "r"(a3), "r"(b0), "r"(b1));
}
__device__ __forceinline__ void cp_async16(uint32_t dst, const void* src) {
    asm volatile("cp.async.cg.shared.global [%0], [%1], 16;" :: "r"(dst), "l"(src));
}

// ---------------- prepasses: fp32 -> tf32 bit patterns ----------------------
__global__ void prep_x(const float4* __restrict__ src)
{
    int i = blockIdx.x * 256 + threadIdx.x;
    if (i < MR * DIMC / 4) {
        float4 v = src[i];
        uint4 o;
        o.x = f2tf32(v.x); o.y = f2tf32(v.y);
        o.z = f2tf32(v.z); o.w = f2tf32(v.w);
        ((uint4*)g_xt)[i] = o;
    }
}
__global__ void prep_w(const float4* __restrict__ wq, const float4* __restrict__ wk,
                       const float4* __restrict__ wv, const float4* __restrict__ wo)
{
    const int n4 = DIMC * DIMC / 4;
    int i = blockIdx.x * 256 + threadIdx.x;
    if (i >= 4 * n4) return;
    int seg = i / n4, r = i - seg * n4;
    const float4* s = (seg == 0) ? wq : (seg == 1) ? wk : (seg == 2) ? wv : wo;
    uint4* d = (seg == 0) ? (uint4*)g_wqt : (seg == 1) ? (uint4*)g_wkt
             : (seg == 2) ? (uint4*)g_wvt : (uint4*)g_wot;
    float4 v = s[r];
    uint4 o;
    o.x = f2tf32(v.x); o.y = f2tf32(v.y);
    o.z = f2tf32(v.z); o.w = f2tf32(v.w);
    d[r] = o;
}
// small weights (eW, pW) -> permuted tf32 dense arrays
__global__ void prep_small(const float* __restrict__ eW, const float* __restrict__ pW)
{
    int i = blockIdx.x * 256 + threadIdx.x;
    if (i >= 2 * 3 * 4096) return;
    int which = i / (3 * 4096);
    int rem   = i - which * (3 * 4096);
    const float* src = which ? pW : eW;
    uint32_t*    dst = which ? g_pwt : g_ewt;
    int rc = rem & 4095;
    int c = rc & 63;
    dst[(rem & ~4095) + (rc & ~63) + ((c & 7) << 3) + (c >> 3)] = f2tf32(src[rem]);
}

// =======================================================================
// Big GEMMs: tf32, 3-stage cp.async pipeline, ONE barrier per k-tile.
// =======================================================================
#define AS_STRIDE 36
#define BS_STRIDE 136
#define AS_TILE   (128 * AS_STRIDE)
#define BS_TILE   (32 * BS_STRIDE)
#define NT        (DIMC / 32)
#define NSTAGE    3
#define GEMM_SMEM_BYTES (NSTAGE * (AS_TILE + BS_TILE) * 4)

#define GEMM_PROLOG \
    extern __shared__ uint32_t smemg[]; \
    uint32_t* Asf = smemg; \
    uint32_t* Bsf = smemg + NSTAGE * AS_TILE; \
    uint32_t As_base = (uint32_t)__cvta_generic_to_shared(Asf); \
    uint32_t Bs_base = (uint32_t)__cvta_generic_to_shared(Bsf); \
    int tid = threadIdx.x; \
    int warp = tid >> 5, lane = tid & 31; \
    int g = lane >> 2, t = lane & 3; \
    int wm = warp >> 1, wn = warp & 1; \
    int a_row = tid >> 1, a_col = (tid & 1) << 4; \
    int b_row = tid >> 3, b_col = (tid & 7) << 4; \
    float acc[2][8][4]; \
    _Pragma("unroll") \
    for (int i = 0; i < 2; i++) \
        _Pragma("unroll") \
        for (int j = 0; j < 8; j++) \
            _Pragma("unroll") \
            for (int q = 0; q < 4; q++) acc[i][j][q] = 0.0f;

#define GEMM_CPLOAD(APTR_BASE, K0, BUF) { \
    const uint32_t* ap_ = (APTR_BASE) + (K0) + a_col; \
    const uint32_t* bp_ = W + (size_t)((K0) + b_row) * DIMC + n0 + b_col; \
    uint32_t asd = As_base + (uint32_t)(((BUF) * AS_TILE + a_row * AS_STRIDE + a_col) * 4); \
    uint32_t bsd = Bs_base + (uint32_t)(((BUF) * BS_TILE + b_row * BS_STRIDE + b_col) * 4); \
    _Pragma("unroll") \
    for (int u = 0; u < 4; u++) { \
        cp_async16(asd + u * 16, ap_ + u * 4); \
        cp_async16(bsd + u * 16, bp_ + u * 4); \
    } }

#define GEMM_COMPUTE(BUF) { \
    const uint32_t* Asc = Asf + (BUF) * AS_TILE; \
    const uint32_t* Bsc = Bsf + (BUF) * BS_TILE; \
    _Pragma("unroll") \
    for (int kk = 0; kk < 4; kk++) { \
        int ks = kk * 8; \
        uint32_t af[2][4]; \
        _Pragma("unroll") \
        for (int i = 0; i < 2; i++) { \
            int rb = wm * 32 + i * 16; \
            af[i][0] = Asc[(rb + g    ) * AS_STRIDE + ks + t    ]; \
            af[i][1] = Asc[(rb + g + 8) * AS_STRIDE + ks + t    ]; \
            af[i][2] = Asc[(rb + g    ) * AS_STRIDE + ks + t + 4]; \
            af[i][3] = Asc[(rb + g + 8) * AS_STRIDE + ks + t + 4]; \
        } \
        uint32_t bf[8][2]; \
        _Pragma("unroll") \
        for (int j = 0; j < 8; j++) { \
            int cb = wn * 64 + j * 8 + g; \
            bf[j][0] = Bsc[(ks + t    ) * BS_STRIDE + cb]; \
            bf[j][1] = Bsc[(ks + t + 4) * BS_STRIDE + cb]; \
        } \
        _Pragma("unroll") \
        for (int i = 0; i < 2; i++) \
            _Pragma("unroll") \
            for (int j = 0; j < 8; j++) \
                mma_tf32(acc[i][j], af[i][0], af[i][1], af[i][2], af[i][3], \
                         bf[j][0], bf[j][1]); \
    } }

// 3-stage: prefetch 0,1; per iter: wait(<=1 outstanding) -> barrier ->
// prefetch kt+2 (overwrites stage (kt-1)%3, safe past barrier) -> compute kt.
#define GEMM_MAINLOOP(APTR_BASE) \
    GEMM_CPLOAD(APTR_BASE, 0, 0) \
    asm volatile("cp.async.commit_group;"); \
    GEMM_CPLOAD(APTR_BASE, 32, 1) \
    asm volatile("cp.async.commit_group;"); \
    _Pragma("unroll 1") \
    for (int kt = 0; kt < NT; kt++) { \
        asm volatile("cp.async.wait_group 1;"); \
        __syncthreads(); \
        if (kt + 2 < NT) { \
            GEMM_CPLOAD(APTR_BASE, (kt + 2) * 32, (kt + 2) % 3) \
            asm volatile("cp.async.commit_group;"); \
        } else { \
            asm volatile("cp.async.commit_group;"); \
        } \
        GEMM_COMPUTE(kt % 3) \
    }

// nb_base lets us launch the q part (base 0, 6 x-tiles) and the k/v part
// (base 6, 12 x-tiles) as separate, overlappable launches.
__global__ __launch_bounds__(256, 2) void qkv_gemm(int nb_base)
{
    GEMM_PROLOG
    int nb   = blockIdx.x + nb_base;
    int wsel = nb / 6;
    const uint32_t* W = (wsel == 0) ? g_wqt : (wsel == 1 ? g_wkt : g_wvt);
    float*          O = (wsel == 0) ? g_q : (wsel == 1 ? g_k : g_v);
    int n0 = (nb % 6) * 128;
    int m0 = blockIdx.y * 128;
    const uint32_t* Abase = g_xt + (size_t)(m0 + a_row) * DIMC;

    GEMM_MAINLOOP(Abase)

#pragma unroll
    for (int i = 0; i < 2; i++) {
#pragma unroll
        for (int j = 0; j < 8; j++) {
            int r0 = m0 + wm * 32 + i * 16 + g;
            int c  = n0 + wn * 64 + j * 8 + t * 2;
            int h = c >> 6, d = c & 63;
#pragma unroll
            for (int half = 0; half < 2; half++) {
                int m = half ? r0 + 8 : r0;
                int b = m >> 12, n = m & 4095;
                float v0 = acc[i][j][half * 2 + 0];
                float v1 = acc[i][j][half * 2 + 1];
                if (wsel < 2) { v0 = fmap_f(v0); v1 = fmap_f(v1); }
                float* dst = O + (((size_t)(b * Hh + h) * Nseq + n) * Dh + d);
                dst[0] = v0; dst[1] = v1;
            }
        }
    }
}

__global__ __launch_bounds__(256, 2) void out_gemm(
    const float* __restrict__ bias, float* __restrict__ out)
{
    GEMM_PROLOG
    int n0 = blockIdx.x * 128;
    int m0 = blockIdx.y * 128;
    const uint32_t* W = g_wot;
    const uint32_t* Abase = (const uint32_t*)g_attn + (size_t)(m0 + a_row) * DIMC;

    GEMM_MAINLOOP(Abase)

#pragma unroll
    for (int i = 0; i < 2; i++) {
#pragma unroll
        for (int j = 0; j < 8; j++) {
            int r0 = m0 + wm * 32 + i * 16 + g;
            int c  = n0 + wn * 64 + j * 8 + t * 2;
            float b0 = bias[c], b1 = bias[c + 1];
            out[(size_t)r0 * DIMC + c]           = acc[i][j][0] + b0;
            out[(size_t)r0 * DIMC + c + 1]       = acc[i][j][1] + b1;
            out[(size_t)(r0 + 8) * DIMC + c]     = acc[i][j][2] + b0;
            out[(size_t)(r0 + 8) * DIMC + c + 1] = acc[i][j][3] + b1;
        }
    }
}

// =======================================================================
// Tensor-core 64-wide MLP machinery — single tf32, permuted W layout.
// Weights are pre-permuted+converted in GLOBAL; loaders are uint4 copies.
// =======================================================================
#define XS_STRIDE 68
#define WS_STRIDE 72
#define POOL_SMEM_FLOATS (256 * XS_STRIDE + 64 * WS_STRIDE + 192)
#define POOL_SMEM_BYTES  (POOL_SMEM_FLOATS * 4)
#define ATTN_SMEM_FLOATS (256 * XS_STRIDE + 2 * 64 * WS_STRIDE + 2 * 192 + 64)
#define ATTN_SMEM_BYTES  (ATTN_SMEM_FLOATS * 4)

// vectorized copy of a pre-permuted 64x64 weight tile into smem (stride rows)
__device__ __forceinline__ void copy_w_smem(
    uint32_t* Wd, const uint32_t* __restrict__ src, int tid)
{
    for (int idx = tid * 4; idx < 4096; idx += 1024) {
        uint4 v = *(const uint4*)(src + idx);
        *(uint4*)(Wd + (idx >> 6) * WS_STRIDE + (idx & 63)) = v;
    }
}

__device__ __forceinline__ void mma_block64(
    float acc[2][8][4], const float* Xw, const uint32_t* Ws, int g, int t)
{
#pragma unroll
    for (int ks8 = 0; ks8 < 8; ks8++) {
        int ks = ks8 * 8;
        uint32_t af[2][4];
#pragma unroll
        for (int i = 0; i < 2; i++) {
            const float* xr = Xw + (i * 16 + g) * XS_STRIDE + ks;
            af[i][0] = f2tf32(xr[t]);
            af[i][1] = f2tf32(xr[8 * XS_STRIDE + t]);
            af[i][2] = f2tf32(xr[t + 4]);
            af[i][3] = f2tf32(xr[8 * XS_STRIDE + t + 4]);
        }
        const uint32_t* w0 = Ws + (ks + t    ) * WS_STRIDE + g * 8;
        const uint32_t* w1 = Ws + (ks + t + 4) * WS_STRIDE + g * 8;
        uint4 b0a = *(const uint4*)w0;
        uint4 b0b = *(const uint4*)(w0 + 4);
        uint4 b1a = *(const uint4*)w1;
        uint4 b1b = *(const uint4*)(w1 + 4);
        uint32_t b0[8] = {b0a.x, b0a.y, b0a.z, b0a.w, b0b.x, b0b.y, b0b.z, b0b.w};
        uint32_t b1[8] = {b1a.x, b1a.y, b1a.z, b1a.w, b1b.x, b1b.y, b1b.z, b1b.w};
#pragma unroll
        for (int j = 0; j < 8; j++)
#pragma unroll
            for (int i = 0; i < 2; i++)
                mma_tf32(acc[i][j], af[i][0], af[i][1], af[i][2], af[i][3],
                         b0[j], b1[j]);
    }
}

__device__ __forceinline__ void ln_gelu_regs(
    float acc[2][8][4], const float* Pb, const float* Pg, const float* Pe, int t)
{
#pragma unroll
    for (int i = 0; i < 2; i++) {
        float s1A = 0, s2A = 0, s1B = 0, s2B = 0;
#pragma unroll
        for (int j = 0; j < 8; j++) {
#pragma unroll
            for (int q = 0; q < 4; q++) {
                int col = j * 8 + t * 2 + (q & 1);
                float v = acc[i][j][q] + Pb[col];
                acc[i][j][q] = v;
                if (q < 2) { s1A += v; s2A += v * v; }
                else       { s1B += v; s2B += v * v; }
            }
        }
        s1A += __shfl_xor_sync(~0u, s1A, 1); s2A += __shfl_xor_sync(~0u, s2A, 1);
        s1B += __shfl_xor_sync(~0u, s1B, 1); s2B += __shfl_xor_sync(~0u, s2B, 1);
        s1A += __shfl_xor_sync(~0u, s1A, 2); s2A += __shfl_xor_sync(~0u, s2A, 2);
        s1B += __shfl_xor_sync(~0u, s1B, 2); s2B += __shfl_xor_sync(~0u, s2B, 2);
        float muA = s1A * (1.0f / 64.0f);
        float muB = s1B * (1.0f / 64.0f);
        float rA = rsqrtf(s2A * (1.0f / 64.0f) - muA * muA + 1e-5f);
        float rB = rsqrtf(s2B * (1.0f / 64.0f) - muB * muB + 1e-5f);
#pragma unroll
        for (int j = 0; j < 8; j++) {
#pragma unroll
            for (int q = 0; q < 4; q++) {
                int col = j * 8 + t * 2 + (q & 1);
                float mu = (q < 2) ? muA : muB;
                float rv = (q < 2) ? rA : rB;
                acc[i][j][q] = gelu_f((acc[i][j][q] - mu) * rv * Pg[col] + Pe[col]);
            }
        }
    }
}

// ---------------- pool stage (tensor core): pair-mean + MLP(LN+gelu) --------
__global__ __launch_bounds__(256, 2) void pool_mlp_tc(
    int stage,
    const float* __restrict__ pb,
    const float* __restrict__ pg, const float* __restrict__ pbe)
{
    extern __shared__ float sm[];
    float*    Xs = sm;
    uint32_t* Ws = (uint32_t*)(sm + 256 * XS_STRIDE);
    float*    Pb = (float*)(Ws + 64 * WS_STRIDE);
    float*    Pg = Pb + 64;
    float*    Pe = Pg + 64;

    const float* in; float* out; int s_in, s_out;
    if (stage == 0)      { in = g_k;   out = g_kcA; s_in = 4096; s_out = 2048; }
    else if (stage == 1) { in = g_kcA; out = g_kcB; s_in = 2048; s_out = 1024; }
    else                 { in = g_kcB; out = g_kcA; s_in = 1024; s_out = 512;  }

    int tid = threadIdx.x, warp = tid >> 5, lane = tid & 31;
    int g = lane >> 2, t = lane & 3;

    for (int idx = tid; idx < 256 * 16; idx += 256) {
        int r = idx >> 4, c4 = (idx & 15) << 2;
        int rg = blockIdx.x * 256 + r;
        int bh = rg / s_out, n = rg - bh * s_out;
        const float* src = in + ((size_t)bh * s_in + 2 * n) * 64 + c4;
        float4 a = *(const float4*)src;
        float4 b = *(const float4*)(src + 64);
        float4 v;
        v.x = 0.5f * (a.x + b.x); v.y = 0.5f * (a.y + b.y);
        v.z = 0.5f * (a.z + b.z); v.w = 0.5f * (a.w + b.w);
        *(float4*)&Xs[r * XS_STRIDE + c4] = v;
    }
    copy_w_smem(Ws, g_pwt + stage * 4096, tid);
    if (tid < 64) {
        Pb[tid] = pb[stage * 64 + tid];
        Pg[tid] = pg[stage * 64 + tid];
        Pe[tid] = pbe[stage * 64 + tid];
    }
    __syncthreads();

    float acc[2][8][4];
#pragma unroll
    for (int i = 0; i < 2; i++)
#pragma unroll
        for (int j = 0; j < 8; j++)
#pragma unroll
            for (int q = 0; q < 4; q++) acc[i][j][q] = 0.0f;

    mma_block64(acc, Xs + warp * 32 * XS_STRIDE, Ws, g, t);
    ln_gelu_regs(acc, Pb, Pg, Pe, t);

    float* ob = out + (size_t)(blockIdx.x * 256 + warp * 32) * 64;
#pragma unroll
    for (int i = 0; i < 2; i++) {
#pragma unroll
        for (int j = 0; j < 8; j++) {
            int col = j * 8 + t * 2;
            float2 v0 = make_float2(acc[i][j][0], acc[i][j][1]);
            float2 v1 = make_float2(acc[i][j][2], acc[i][j][3]);
            *(float2*)(ob + (i * 16 + g    ) * 64 + col) = v0;
            *(float2*)(ob + (i * 16 + g + 8) * 64 + col) = v1;
        }
    }
}

// ---------------- fused attention apply + 3 exp MLP stages ------------------
// 256 rows/block, double-buffered weight copies from pre-permuted global.
__global__ __launch_bounds__(256, 2) void attn_mlp_tc(
    const float* __restrict__ eb,
    const float* __restrict__ eg, const float* __restrict__ ebe)
{
    extern __shared__ float sm[];
    float*    Xs  = sm;
    uint32_t* Wb  = (uint32_t*)(sm + 256 * XS_STRIDE);       // 2 buffers
    float*    Pp  = (float*)(Wb + 2 * 64 * WS_STRIDE);       // 2 x 192
    float*    Ksm = Pp + 2 * 192;

    int tid = threadIdx.x, warp = tid >> 5, lane = tid & 31;
    int g = lane >> 2, t = lane & 3;
    int bh = blockIdx.x >> 4;
    int n0 = (blockIdx.x & 15) << 8;

    const float* qb = g_q + ((size_t)bh * 4096 + n0) * 64;
    for (int idx = tid; idx < 256 * 16; idx += 256) {
        int r = idx >> 4, c4 = (idx & 15) << 2;
        *(float4*)&Xs[r * XS_STRIDE + c4] = *(const float4*)(qb + r * 64 + c4);
    }
    copy_w_smem(Wb, g_kvt + bh * 4096, tid);                 // buf0 <- kv
    if (tid < 64) Ksm[tid] = g_ksum[bh * 64 + tid];
    __syncthreads();

    const float* Xw  = Xs + warp * 32 * XS_STRIDE;
    float*       Xwm = Xs + warp * 32 * XS_STRIDE;

    // preload stage s=2 into buf1 (overlaps with q@kv compute)
    copy_w_smem(Wb + 64 * WS_STRIDE, g_ewt + 2 * 4096, tid);
    if (tid < 64) {
        Pp[192 + tid]       = eb[2 * 64 + tid];
        Pp[192 + 64 + tid]  = eg[2 * 64 + tid];
        Pp[192 + 128 + tid] = ebe[2 * 64 + tid];
    }

    float acc[2][8][4];
#pragma unroll
    for (int i = 0; i < 2; i++)
#pragma unroll
        for (int j = 0; j < 8; j++)
#pragma unroll
            for (int q = 0; q < 4; q++) acc[i][j][q] = 0.0f;

    mma_block64(acc, Xw, Wb, g, t);

    float inv2[2][2];
#pragma unroll
    for (int i = 0; i < 2; i++) {
#pragma unroll
        for (int hlf = 0; hlf < 2; hlf++) {
            const float* xr = Xw + (i * 16 + g + hlf * 8) * XS_STRIDE;
            float dp = 0.0f;
#pragma unroll
            for (int e = 0; e < 16; e++) dp += xr[t + e * 4] * Ksm[t + e * 4];
            dp += __shfl_xor_sync(~0u, dp, 1);
            dp += __shfl_xor_sync(~0u, dp, 2);
            inv2[i][hlf] = 1.0f / (dp + 1e-6f);
        }
    }
#pragma unroll
    for (int i = 0; i < 2; i++) {
#pragma unroll
        for (int j = 0; j < 8; j++) {
            int col = j * 8 + t * 2;
            float2 v0 = make_float2(acc[i][j][0] * inv2[i][0], acc[i][j][1] * inv2[i][0]);
            float2 v1 = make_float2(acc[i][j][2] * inv2[i][1], acc[i][j][3] * inv2[i][1]);
            *(float2*)&Xwm[(i * 16 + g    ) * XS_STRIDE + col] = v0;
            *(float2*)&Xwm[(i * 16 + g + 8) * XS_STRIDE + col] = v1;
        }
    }
    __syncthreads();   // buf1 (s=2) ready; all reads of buf0 done

    int b = bh / Hh, h = bh - b * Hh;
    float* obase = g_attn + ((size_t)b * 4096 + n0 + warp * 32) * DIMC + h * 64;

#pragma unroll 1
    for (int s = 2; s >= 0; s--) {
        int buf = (s == 1) ? 0 : 1;
        if (s > 0) {
            copy_w_smem(Wb + (1 - buf) * 64 * WS_STRIDE, g_ewt + (s - 1) * 4096, tid);
            if (tid < 64) {
                float* Pd = Pp + (1 - buf) * 192;
                Pd[tid]       = eb[(s - 1) * 64 + tid];
                Pd[64 + tid]  = eg[(s - 1) * 64 + tid];
                Pd[128 + tid] = ebe[(s - 1) * 64 + tid];
            }
        }

#pragma unroll
        for (int i = 0; i < 2; i++)
#pragma unroll
            for (int j = 0; j < 8; j++)
#pragma unroll
                for (int q = 0; q < 4; q++) acc[i][j][q] = 0.0f;

        const float* Pd = Pp + buf * 192;
        mma_block64(acc, Xw, Wb + buf * 64 * WS_STRIDE, g, t);
        ln_gelu_regs(acc, Pd, Pd + 64, Pd + 128, t);

        if (s > 0) {
#pragma unroll
            for (int i = 0; i < 2; i++) {
#pragma unroll
                for (int j = 0; j < 8; j++) {
                    int col = j * 8 + t * 2;
                    *(float2*)&Xwm[(i * 16 + g    ) * XS_STRIDE + col] =
                        make_float2(acc[i][j][0], acc[i][j][1]);
                    *(float2*)&Xwm[(i * 16 + g + 8) * XS_STRIDE + col] =
                        make_float2(acc[i][j][2], acc[i][j][3]);
                }
            }
            __syncthreads();
        } else {
            // final stage: store tf32 bit-patterns for out_gemm
#pragma unroll
            for (int i = 0; i < 2; i++) {
#pragma unroll
                for (int j = 0; j < 8; j++) {
                    int col = j * 8 + t * 2;
                    *(float2*)(obase + (size_t)(i * 16 + g    ) * DIMC + col) =
                        make_float2(__uint_as_float(f2tf32(acc[i][j][0])),
                                    __uint_as_float(f2tf32(acc[i][j][1])));
                    *(float2*)(obase + (size_t)(i * 16 + g + 8) * DIMC + col) =
                        make_float2(__uint_as_float(f2tf32(acc[i][j][2])),
                                    __uint_as_float(f2tf32(acc[i][j][3])));
                }
            }
        }
    }
}

// ---------------- vc pooling: mean over 8 consecutive tokens ----------------
__global__ void vpool_kernel()
{
    int idx = blockIdx.x * 256 + threadIdx.x;
    if (idx >= BH * 512 * Dh) return;
    int d   = idx & 63;
    int rest = idx >> 6;
    int n   = rest & 511;
    int bh  = rest >> 9;
    const float* src = g_v + (bh * 4096 + n * 8) * 64 + d;
    float s = 0.0f;
#pragma unroll
    for (int j = 0; j < 8; j++) s += src[j * 64];
    g_vc[idx] = s * 0.125f;
}

// ---------------- kv = (kc/sqrt(512))^T vc + k_sum; stores permuted tf32 ----
__global__ __launch_bounds__(256) void kv_kernel()
{
    int bh = blockIdx.x;
    __shared__ float ks[64][65];
    __shared__ float vs[64][65];
    int tid = threadIdx.x;
    int td = tid & 15, te = tid >> 4;
    float acc[4][4];
#pragma unroll
    for (int i = 0; i < 4; i++)
#pragma unroll
        for (int j = 0; j < 4; j++) acc[i][j] = 0.0f;
    float colsum = 0.0f;
    const float scale = rsqrtf(512.0f);

    for (int nt = 0; nt < 512; nt += 64) {
        for (int i = tid; i < 4096; i += 256) {
            int rr = i >> 6, cc = i & 63;
            ks[rr][cc] = g_kcA[(bh * 512 + nt + rr) * 64 + cc] * scale;
            vs[rr][cc] = g_vc [(bh * 512 + nt + rr) * 64 + cc];
        }
        __syncthreads();
        if (tid < 64) {
            for (int rr = 0; rr < 64; rr++) colsum += ks[rr][tid];
        }
#pragma unroll 4
        for (int nn = 0; nn < 64; nn++) {
            float a[4], bb[4];
#pragma unroll
            for (int i = 0; i < 4; i++) a[i]  = ks[nn][td * 4 + i];
#pragma unroll
            for (int j = 0; j < 4; j++) bb[j] = vs[nn][te * 4 + j];
#pragma unroll
            for (int i = 0; i < 4; i++)
#pragma unroll
                for (int j = 0; j < 4; j++)
                    acc[i][j] = fmaf(a[i], bb[j], acc[i][j]);
        }
        __syncthreads();
    }
    // store permuted tf32 bits: row r (k-dim), col c -> r*64 + (c%8)*8 + c/8
#pragma unroll
    for (int i = 0; i < 4; i++) {
#pragma unroll
        for (int j = 0; j < 4; j++) {
            int r = td * 4 + i, c = te * 4 + j;
            g_kvt[bh * 4096 + r * 64 + ((c & 7) << 3) + (c >> 3)] = f2tf32(acc[i][j]);
        }
    }
    if (tid < 64) g_ksum[bh * 64 + tid] = colsum;
}

// ---------------- launch --------------------------------------------------
extern "C" void kernel_launch(void* const* d_in, const int* in_sizes, int n_in,
                              void* d_out, int out_size)
{
    const float* x   = (const float*)d_in[0];
    const float* Wq  = (const float*)d_in[1];
    const float* Wk  = (const float*)d_in[2];
    const float* Wv  = (const float*)d_in[3];
    const float* pW  = (const float*)d_in[4];
    const float* pb  = (const float*)d_in[5];
    const float* pg  = (const float*)d_in[6];
    const float* pbe = (const float*)d_in[7];
    const float* eW  = (const float*)d_in[8];
    const float* eb  = (const float*)d_in[9];
    const float* eg  = (const float*)d_in[10];
    const float* ebe = (const float*)d_in[11];
    const float* Wo  = (const float*)d_in[12];
    const float* bo  = (const float*)d_in[13];
    float* out = (float*)d_out;

    static cudaStream_t s2 = nullptr;
    static cudaEvent_t evFork = nullptr, evJoin = nullptr;
    if (s2 == nullptr) {
        cudaStreamCreateWithFlags(&s2, cudaStreamNonBlocking);
        cudaEventCreateWithFlags(&evFork, cudaEventDisableTiming);
        cudaEventCreateWithFlags(&evJoin, cudaEventDisableTiming);
        cudaFuncSetAttribute(qkv_gemm,
            cudaFuncAttributeMaxDynamicSharedMemorySize, GEMM_SMEM_BYTES);
        cudaFuncSetAttribute(out_gemm,
            cudaFuncAttributeMaxDynamicSharedMemorySize, GEMM_SMEM_BYTES);
        cudaFuncSetAttribute(pool_mlp_tc,
            cudaFuncAttributeMaxDynamicSharedMemorySize, POOL_SMEM_BYTES);
        cudaFuncSetAttribute(attn_mlp_tc,
            cudaFuncAttributeMaxDynamicSharedMemorySize, ATTN_SMEM_BYTES);
    }

    prep_x<<<(MR * DIMC / 4 + 255) / 256, 256>>>((const float4*)x);
    prep_w<<<(4 * DIMC * DIMC / 4 + 255) / 256, 256>>>(
        (const float4*)Wq, (const float4*)Wk, (const float4*)Wv, (const float4*)Wo);
    prep_small<<<(2 * 3 * 4096 + 255) / 256, 256>>>(eW, pW);

    // k/v projections first (pool chain depends only on these)
    qkv_gemm<<<dim3(12, MR / 128), 256, GEMM_SMEM_BYTES>>>(6);

    // fork: pool chain on s2, concurrent with q projection on stream 0
    cudaEventRecord(evFork, 0);
    cudaStreamWaitEvent(s2, evFork, 0);

    vpool_kernel<<<(BH * 512 * Dh + 255) / 256, 256, 0, s2>>>();
    pool_mlp_tc<<<BH * 2048 / 256, 256, POOL_SMEM_BYTES, s2>>>(0, pb, pg, pbe);
    pool_mlp_tc<<<BH * 1024 / 256, 256, POOL_SMEM_BYTES, s2>>>(1, pb, pg, pbe);
    pool_mlp_tc<<<BH * 512 / 256, 256, POOL_SMEM_BYTES, s2>>>(2, pb, pg, pbe);
    kv_kernel<<<BH, 256, 0, s2>>>();
    cudaEventRecord(evJoin, s2);

    // q projection overlaps the pool chain
    qkv_gemm<<<dim3(6, MR / 128), 256, GEMM_SMEM_BYTES>>>(0);

    // join: attn needs g_q (stream 0) AND g_kvt/g_ksum (s2)
    cudaStreamWaitEvent(0, evJoin, 0);
    attn_mlp_tc<<<BH * 16, 256, ATTN_SMEM_BYTES>>>(eb, eg, ebe);
    out_gemm<<<dim3(6, MR / 128), 256, GEMM_SMEM_BYTES>>>(bo, out);
}